// round 1
// baseline (speedup 1.0000x reference)
#include <cuda_runtime.h>
#include <cuda_bf16.h>
#include <math.h>

// ---------------- problem constants ----------------
#define BB   16
#define SS   408
#define DD   512
#define LL   10
#define FFN  2048
#define HH   8
#define DH   64
#define CHK  68
#define NCHUNK (SS/CHK)     // 6
#define MROWS (BB*SS)       // 6528
#define EPS  1e-5f

// ---------------- scratch (no allocations allowed) ----------------
// h,q,k,v,g,ret : 6 * MROWS*DD   +  ff : MROWS*FFN
__device__ float g_scratch[(size_t)6 * MROWS * DD + (size_t)MROWS * FFN];

// ---------------- embedding gather ----------------
__global__ void embed_kernel(const int* __restrict__ tokens,
                             const float* __restrict__ emb,
                             float* __restrict__ x)
{
    int row = blockIdx.x;                 // b*S + s
    int tok = tokens[row];
    const float2* src = (const float2*)(emb + (size_t)tok * DD);
    float2* dst = (float2*)(x + (size_t)row * DD);
    dst[threadIdx.x] = src[threadIdx.x];  // 256 threads * float2 = 512
}

// ---------------- layer norm (one block per row, D=512) ----------------
__global__ void layernorm_kernel(const float* __restrict__ x,
                                 const float* __restrict__ w,
                                 const float* __restrict__ b,
                                 float* __restrict__ out)
{
    int row = blockIdx.x;
    int tid = threadIdx.x;                // 256
    const float* xr = x + (size_t)row * DD;
    float v0 = xr[tid], v1 = xr[tid + 256];
    float s = v0 + v1, ss = v0*v0 + v1*v1;
    __shared__ float rs[8], rss[8];
    #pragma unroll
    for (int o = 16; o; o >>= 1) {
        s  += __shfl_xor_sync(0xffffffffu, s,  o);
        ss += __shfl_xor_sync(0xffffffffu, ss, o);
    }
    if ((tid & 31) == 0) { rs[tid >> 5] = s; rss[tid >> 5] = ss; }
    __syncthreads();
    float tot = 0.f, tots = 0.f;
    #pragma unroll
    for (int i = 0; i < 8; i++) { tot += rs[i]; tots += rss[i]; }
    float mean = tot * (1.f / DD);
    float var  = tots * (1.f / DD) - mean * mean;
    float rstd = rsqrtf(var + EPS);
    float* orow = out + (size_t)row * DD;
    orow[tid]       = (v0 - mean) * rstd * w[tid]       + b[tid];
    orow[tid + 256] = (v1 - mean) * rstd * w[tid + 256] + b[tid + 256];
}

// ---------------- rotary (handles the pair (d, d+32) per thread) -------
__global__ void rotary_kernel(float* __restrict__ t, float scale, int total)
{
    int idx = blockIdx.x * blockDim.x + threadIdx.x;   // over MROWS*H*32
    if (idx >= total) return;
    int j   = idx & 31;
    int hh  = (idx >> 5) & 7;
    int row = idx >> 8;                  // b*S + s
    int s   = row % SS;
    float inv = powf(10000.f, -2.f * (float)j / 64.f);
    float ang = (float)s * inv;
    float sn, cs;
    sincosf(ang, &sn, &cs);
    int base = row * DD + hh * DH + j;
    float t1 = t[base], t2 = t[base + 32];
    t[base]      = (t1 * cs - t2 * sn) * scale;
    t[base + 32] = (t2 * cs + t1 * sn) * scale;
}

// ---------------- SGEMM: C[M,N] (+)= A[M,K] @ B[K,N] + bias ------------
// epi: 0 = write, 1 = silu then write, 2 = add to existing C then write
// Requires M%128==0, N%128==0, K%16==0 (holds for all calls here).
__global__ void __launch_bounds__(256, 2)
sgemm_kernel(const float* __restrict__ A,
             const float* __restrict__ Bm,
             const float* __restrict__ bias,
             float* __restrict__ C,
             int M, int N, int K, int epi)
{
    const int BM = 128, BN = 128, BK = 16, TM = 8, TN = 8;
    __shared__ float As[BK][BM];
    __shared__ float Bs[BK][BN];
    int tid = threadIdx.x;               // 256
    int tx = tid & 15;
    int ty = tid >> 4;
    const float* Ab = A  + (size_t)blockIdx.y * BM * K;
    const float* Bb = Bm + (size_t)blockIdx.x * BN;
    float acc[TM][TN] = {};

    int aRow = tid >> 2;                 // 0..63
    int aCol = (tid & 3) << 2;           // 0,4,8,12
    int bRow = tid >> 5;                 // 0..7
    int bCol = (tid & 31) << 2;          // 0..124

    for (int k0 = 0; k0 < K; k0 += BK) {
        #pragma unroll
        for (int i = 0; i < 2; i++) {
            int r = aRow + i * 64;
            float4 t = *(const float4*)(Ab + (size_t)r * K + k0 + aCol);
            As[aCol + 0][r] = t.x;
            As[aCol + 1][r] = t.y;
            As[aCol + 2][r] = t.z;
            As[aCol + 3][r] = t.w;
        }
        #pragma unroll
        for (int i = 0; i < 2; i++) {
            int r = bRow + i * 8;
            *(float4*)(&Bs[r][bCol]) = *(const float4*)(Bb + (size_t)(k0 + r) * N + bCol);
        }
        __syncthreads();
        #pragma unroll
        for (int kk = 0; kk < BK; kk++) {
            float a[TM], bv[TN];
            *(float4*)&a[0]  = *(float4*)&As[kk][ty * TM];
            *(float4*)&a[4]  = *(float4*)&As[kk][ty * TM + 4];
            *(float4*)&bv[0] = *(float4*)&Bs[kk][tx * TN];
            *(float4*)&bv[4] = *(float4*)&Bs[kk][tx * TN + 4];
            #pragma unroll
            for (int i = 0; i < TM; i++)
                #pragma unroll
                for (int j = 0; j < TN; j++)
                    acc[i][j] += a[i] * bv[j];
        }
        __syncthreads();
    }

    int row0 = blockIdx.y * BM + ty * TM;
    int col0 = blockIdx.x * BN + tx * TN;
    #pragma unroll
    for (int i = 0; i < TM; i++) {
        float* Crow = C + (size_t)(row0 + i) * N;
        #pragma unroll
        for (int j = 0; j < TN; j++) {
            float v = acc[i][j] + bias[col0 + j];
            if (epi == 1)      v = v / (1.f + expf(-v));
            else if (epi == 2) v += Crow[col0 + j];
            Crow[col0 + j] = v;
        }
    }
}

// ---------------- chunkwise retention: one CTA per (b, head) -----------
// smem: q,k,v chunks [68][64], state [64][64], inner [68][68]
__global__ void retention_kernel(const float* __restrict__ q,
                                 const float* __restrict__ k,
                                 const float* __restrict__ v,
                                 float* __restrict__ ret)
{
    extern __shared__ float sm[];
    float* sq    = sm;                       // 68*64
    float* sk    = sq + CHK * DH;            // 68*64
    float* sv    = sk + CHK * DH;            // 68*64
    float* st    = sv + CHK * DH;            // 64*64 state[d_in][d_out]
    float* inner = st + DH * DH;             // 68*68
    __shared__ float gpow[CHK + 1];

    int bh = blockIdx.x;                     // b*H + h
    int b  = bh >> 3;
    int hh = bh & 7;
    int tid = threadIdx.x;                   // 256
    float gamma = 1.f - exp2f(-5.f - (float)hh);
    if (tid <= CHK) gpow[tid] = powf(gamma, (float)tid);
    for (int i = tid; i < DH * DH; i += 256) st[i] = 0.f;
    __syncthreads();
    float chunk_dec = gpow[CHK];             // gamma^68

    for (int c = 0; c < NCHUNK; c++) {
        int base = ((b * SS + c * CHK) * HH + hh) * DH;  // elem (i=0,d=0); row stride 512
        for (int i = tid; i < CHK * DH; i += 256) {
            int r = i >> 6, d = i & 63;
            int g = base + r * DD + d;
            sq[i] = q[g];
            sk[i] = k[g];
            sv[i] = v[g];
        }
        __syncthreads();

        // inner[i][j] = (q_i . k_j) * gamma^(i-j)   (i>=j)
        for (int e = tid; e < CHK * CHK; e += 256) {
            int i = e / CHK, j = e - i * CHK;
            float s = 0.f;
            if (i >= j) {
                const float* qi = sq + i * DH;
                const float* kj = sk + j * DH;
                #pragma unroll 16
                for (int d = 0; d < DH; d++) s += qi[d] * kj[d];
                s *= gpow[i - j];
            }
            inner[e] = s;
        }
        __syncthreads();

        // out[i][d] = sum_{j<=i} inner[i][j]*v[j][d] + (q_i . state[:,d]) * gamma^(i+1)
        for (int e = tid; e < CHK * DH; e += 256) {
            int i = e >> 6, d = e & 63;
            float s = 0.f;
            const float* in_i = inner + i * CHK;
            for (int j = 0; j <= i; j++) s += in_i[j] * sv[j * DH + d];
            float s2 = 0.f;
            const float* qi = sq + i * DH;
            #pragma unroll 16
            for (int ee = 0; ee < DH; ee++) s2 += qi[ee] * st[ee * DH + d];
            s += s2 * (gamma * gpow[i]);
            ret[base + i * DD + d] = s;
        }
        __syncthreads();

        // state[d][e] = state[d][e]*gamma^C + sum_j k[j][d]*gamma^(C-1-j)*v[j][e]
        for (int e = tid; e < DH * DH; e += 256) {
            int d = e >> 6, e2 = e & 63;
            float s = st[e] * chunk_dec;
            for (int j = 0; j < CHK; j++)
                s += sk[j * DH + d] * gpow[CHK - 1 - j] * sv[j * DH + e2];
            st[e] = s;
        }
        __syncthreads();
    }
}

// ---------------- per-head group norm fused with gate ------------------
// g (already silu'd) becomes g * groupnorm(ret)
__global__ void gnorm_gate_kernel(const float* __restrict__ ret,
                                  const float* __restrict__ gnw,
                                  const float* __restrict__ gnb,
                                  float* __restrict__ g)
{
    int grp  = blockIdx.x;                 // (b*S+s)*H + h
    int hh   = grp & 7;
    int base = (grp >> 3) * DD + hh * DH;
    int lane = threadIdx.x;                // 32
    float v0 = ret[base + lane], v1 = ret[base + lane + 32];
    float s = v0 + v1, ss = v0 * v0 + v1 * v1;
    #pragma unroll
    for (int o = 16; o; o >>= 1) {
        s  += __shfl_xor_sync(0xffffffffu, s,  o);
        ss += __shfl_xor_sync(0xffffffffu, ss, o);
    }
    float mean = s * (1.f / DH);
    float var  = ss * (1.f / DH) - mean * mean;
    float rstd = rsqrtf(var + EPS);
    int wi = hh * DH + lane;
    float o0 = (v0 - mean) * rstd * gnw[wi]      + gnb[wi];
    float o1 = (v1 - mean) * rstd * gnw[wi + 32] + gnb[wi + 32];
    g[base + lane]      *= o0;
    g[base + lane + 32] *= o1;
}

// ---------------- host orchestration ----------------
extern "C" void kernel_launch(void* const* d_in, const int* in_sizes, int n_in,
                              void* d_out, int out_size)
{
    const int*   tokens = (const int*)  d_in[0];
    const float* emb    = (const float*)d_in[1];
    const float* Wq = (const float*)d_in[2],  * bq = (const float*)d_in[3];
    const float* Wk = (const float*)d_in[4],  * bk = (const float*)d_in[5];
    const float* Wv = (const float*)d_in[6],  * bv = (const float*)d_in[7];
    const float* Wg = (const float*)d_in[8],  * bg = (const float*)d_in[9];
    const float* Wo = (const float*)d_in[10], * bo = (const float*)d_in[11];
    const float* gnw  = (const float*)d_in[12], * gnb  = (const float*)d_in[13];
    const float* ln1w = (const float*)d_in[14], * ln1b = (const float*)d_in[15];
    const float* ln2w = (const float*)d_in[16], * ln2b = (const float*)d_in[17];
    const float* w1 = (const float*)d_in[18], * b1 = (const float*)d_in[19];
    const float* w2 = (const float*)d_in[20], * b2 = (const float*)d_in[21];

    float* x = (float*)d_out;                       // [MROWS, D] lives in d_out

    float* base = nullptr;
    cudaGetSymbolAddress((void**)&base, g_scratch);
    const size_t SZ = (size_t)MROWS * DD;
    float* h   = base;
    float* q   = base + SZ;
    float* k   = base + 2 * SZ;
    float* v   = base + 3 * SZ;
    float* g   = base + 4 * SZ;
    float* ret = base + 5 * SZ;
    float* ff  = base + 6 * SZ;                     // MROWS * FFN

    const int RET_SMEM = (3 * CHK * DH + DH * DH + CHK * CHK) * (int)sizeof(float);
    cudaFuncSetAttribute(retention_kernel,
                         cudaFuncAttributeMaxDynamicSharedMemorySize, RET_SMEM);

    dim3 gemmD(DD / 128, MROWS / 128);              // (4, 51)
    dim3 gemmF(FFN / 128, MROWS / 128);             // (16, 51)
    int rotTotal = MROWS * HH * 32;
    int rotBlocks = (rotTotal + 255) / 256;

    embed_kernel<<<MROWS, 256>>>(tokens, emb, x);

    for (int l = 0; l < LL; l++) {
        const size_t oD  = (size_t)l * DD * DD;
        const size_t oF1 = (size_t)l * DD * FFN;
        const size_t oF2 = (size_t)l * FFN * DD;
        const size_t ob  = (size_t)l * DD;
        const size_t obf = (size_t)l * FFN;

        layernorm_kernel<<<MROWS, 256>>>(x, ln1w + ob, ln1b + ob, h);

        sgemm_kernel<<<gemmD, 256>>>(h, Wq + oD, bq + ob, q, MROWS, DD, DD, 0);
        sgemm_kernel<<<gemmD, 256>>>(h, Wk + oD, bk + ob, k, MROWS, DD, DD, 0);
        sgemm_kernel<<<gemmD, 256>>>(h, Wv + oD, bv + ob, v, MROWS, DD, DD, 0);
        sgemm_kernel<<<gemmD, 256>>>(h, Wg + oD, bg + ob, g, MROWS, DD, DD, 1); // silu

        rotary_kernel<<<rotBlocks, 256>>>(q, 1.f, rotTotal);
        rotary_kernel<<<rotBlocks, 256>>>(k, 0.125f, rotTotal);   // dh^-0.5 = 1/8

        retention_kernel<<<BB * HH, 256, RET_SMEM>>>(q, k, v, ret);

        gnorm_gate_kernel<<<MROWS * HH, 32>>>(ret, gnw + ob, gnb + ob, g);

        sgemm_kernel<<<gemmD, 256>>>(g, Wo + oD, bo + ob, x, MROWS, DD, DD, 2); // x += ..

        layernorm_kernel<<<MROWS, 256>>>(x, ln2w + ob, ln2b + ob, h);
        sgemm_kernel<<<gemmF, 256>>>(h, w1 + oF1, b1 + obf, ff, MROWS, FFN, DD, 1); // silu
        sgemm_kernel<<<gemmD, 256>>>(ff, w2 + oF2, b2 + ob, x, MROWS, DD, FFN, 2);  // x += ..
    }
}

// round 3
// speedup vs baseline: 1.8787x; 1.8787x over previous
#include <cuda_runtime.h>
#include <cuda_bf16.h>
#include <math.h>
#include <stdint.h>

// ---------------- problem constants ----------------
#define BB   16
#define SS   408
#define DD   512
#define LL   10
#define FFN  2048
#define HH   8
#define DH   64
#define CHK  68
#define NCHUNK (SS/CHK)     // 6
#define MROWS (BB*SS)       // 6528
#define EPS  1e-5f

// ---------------- scratch (no allocations allowed) ----------------
// fp32: q, k, v, gate, ret  (5 * MROWS*DD)
__device__ __align__(16) float g_scratch[(size_t)5 * MROWS * DD];
// bf16 activations hi/lo: h(2) + g(2) + ff(8)  in units of MROWS*DD
__device__ __align__(16) __nv_bfloat16 g_act[(size_t)12 * MROWS * DD];
// bf16 hi/lo pre-transposed weights: [N][K] K-major per layer
#define W5  ((size_t)LL * DD * DD)
#define WF  ((size_t)LL * DD * FFN)
__device__ __align__(16) __nv_bfloat16 g_wts[10 * W5 + 4 * WF];

// ================= PTX helpers (family-portable: sm_80+) =================
__device__ __forceinline__ uint32_t smem_u32(const void* p) {
    uint32_t a;
    asm("{ .reg .u64 t; cvta.to.shared.u64 t, %1; cvt.u32.u64 %0, t; }"
        : "=r"(a) : "l"(p));
    return a;
}
__device__ __forceinline__ void cp16(uint32_t dst, const void* src) {
    asm volatile("cp.async.cg.shared.global [%0], [%1], 16;"
                 :: "r"(dst), "l"(src));
}
#define CP_COMMIT() asm volatile("cp.async.commit_group;" ::: "memory")
#define CP_WAIT(n)  asm volatile("cp.async.wait_group %0;" :: "n"(n) : "memory")

__device__ __forceinline__ void ldsm4(uint32_t* r, uint32_t addr) {
    asm volatile("ldmatrix.sync.aligned.m8n8.x4.shared.b16 {%0,%1,%2,%3}, [%4];"
                 : "=r"(r[0]), "=r"(r[1]), "=r"(r[2]), "=r"(r[3]) : "r"(addr));
}
__device__ __forceinline__ void mma_bf16(float* c, const uint32_t* a,
                                         uint32_t b0, uint32_t b1) {
    asm volatile(
        "mma.sync.aligned.m16n8k16.row.col.f32.bf16.bf16.f32 "
        "{%0,%1,%2,%3}, {%4,%5,%6,%7}, {%8,%9}, {%0,%1,%2,%3};"
        : "+f"(c[0]), "+f"(c[1]), "+f"(c[2]), "+f"(c[3])
        : "r"(a[0]), "r"(a[1]), "r"(a[2]), "r"(a[3]), "r"(b0), "r"(b1));
}

// ---------------- embedding gather ----------------
__global__ void embed_kernel(const int* __restrict__ tokens,
                             const float* __restrict__ emb,
                             float* __restrict__ x)
{
    int row = blockIdx.x;
    int tok = tokens[row];
    const float2* src = (const float2*)(emb + (size_t)tok * DD);
    float2* dst = (float2*)(x + (size_t)row * DD);
    dst[threadIdx.x] = src[threadIdx.x];
}

// ---------------- layer norm -> bf16 hi/lo split ----------------
__global__ void layernorm_split_kernel(const float* __restrict__ x,
                                       const float* __restrict__ w,
                                       const float* __restrict__ b,
                                       __nv_bfloat16* __restrict__ hi,
                                       __nv_bfloat16* __restrict__ lo)
{
    int row = blockIdx.x;
    int tid = threadIdx.x;                 // 256
    const float* xr = x + (size_t)row * DD;
    float v0 = xr[tid], v1 = xr[tid + 256];
    float s = v0 + v1, ss = v0*v0 + v1*v1;
    __shared__ float rs[8], rss[8];
    #pragma unroll
    for (int o = 16; o; o >>= 1) {
        s  += __shfl_xor_sync(0xffffffffu, s,  o);
        ss += __shfl_xor_sync(0xffffffffu, ss, o);
    }
    if ((tid & 31) == 0) { rs[tid >> 5] = s; rss[tid >> 5] = ss; }
    __syncthreads();
    float tot = 0.f, tots = 0.f;
    #pragma unroll
    for (int i = 0; i < 8; i++) { tot += rs[i]; tots += rss[i]; }
    float mean = tot * (1.f / DD);
    float var  = tots * (1.f / DD) - mean * mean;
    float rstd = rsqrtf(var + EPS);
    float o0 = (v0 - mean) * rstd * w[tid]       + b[tid];
    float o1 = (v1 - mean) * rstd * w[tid + 256] + b[tid + 256];
    size_t base = (size_t)row * DD;
    __nv_bfloat16 h0 = __float2bfloat16(o0);
    __nv_bfloat16 h1 = __float2bfloat16(o1);
    hi[base + tid]       = h0;
    hi[base + tid + 256] = h1;
    lo[base + tid]       = __float2bfloat16(o0 - __bfloat162float(h0));
    lo[base + tid + 256] = __float2bfloat16(o1 - __bfloat162float(h1));
}

// ---------------- rotary ----------------
__global__ void rotary_kernel(float* __restrict__ t, float scale, int total)
{
    int idx = blockIdx.x * blockDim.x + threadIdx.x;
    if (idx >= total) return;
    int j   = idx & 31;
    int hh  = (idx >> 5) & 7;
    int row = idx >> 8;
    int s   = row % SS;
    float inv = powf(10000.f, -2.f * (float)j / 64.f);
    float ang = (float)s * inv;
    float sn, cs;
    sincosf(ang, &sn, &cs);
    int base = row * DD + hh * DH + j;
    float t1 = t[base], t2 = t[base + 32];
    t[base]      = (t1 * cs - t2 * sn) * scale;
    t[base + 32] = (t2 * cs + t1 * sn) * scale;
}

// ---------------- weight transpose + bf16 hi/lo split --------------
// src: [L][K][N] fp32 ; dst hi/lo: [L][N][K] bf16
__global__ void wconv_kernel(const float* __restrict__ src,
                             __nv_bfloat16* __restrict__ hi,
                             __nv_bfloat16* __restrict__ lo,
                             int K, int N)
{
    __shared__ float t[32][33];
    int n0 = blockIdx.x * 32, k0 = blockIdx.y * 32;
    const float* s = src + (size_t)blockIdx.z * K * N;
    int tx = threadIdx.x, ty = threadIdx.y;
    #pragma unroll
    for (int r = ty; r < 32; r += 8)
        t[r][tx] = s[(size_t)(k0 + r) * N + n0 + tx];
    __syncthreads();
    size_t dbase = (size_t)blockIdx.z * N * K;
    #pragma unroll
    for (int r = ty; r < 32; r += 8) {
        float x = t[tx][r];              // element (k0+tx, n0+r)
        __nv_bfloat16 h = __float2bfloat16(x);
        float rem = x - __bfloat162float(h);
        size_t o = dbase + (size_t)(n0 + r) * K + k0 + tx;
        hi[o] = h;
        lo[o] = __float2bfloat16(rem);
    }
}

// ---------------- tensor-core GEMM via mma.sync (bf16 3-term) ----------
// C[M,N] (+)= A[M,K] @ W[K,N] + bias
// A hi/lo: [M][K] bf16 row-major.  B hi/lo: [N][K] bf16 K-major.
// epi: 0 = write fp32, 1 = silu fp32, 2 = add to existing fp32,
//      3 = silu then bf16 hi/lo split into Ch/Cl
#define SA_H 0
#define SA_L 10240
#define SB_H 20480
#define SB_L 30720
#define GSTG 40960
#define GEMM_SMEM (2 * GSTG)

__global__ void __launch_bounds__(256)
tc_gemm(const __nv_bfloat16* __restrict__ Ah,
        const __nv_bfloat16* __restrict__ Al,
        const __nv_bfloat16* __restrict__ Bh,
        const __nv_bfloat16* __restrict__ Bl,
        const float* __restrict__ bias,
        float* __restrict__ C,
        __nv_bfloat16* __restrict__ Ch,
        __nv_bfloat16* __restrict__ Cl,
        int K, int N, int epi)
{
    extern __shared__ char sm[];
    uint32_t sb = smem_u32(sm);
    int tid = threadIdx.x;
    int lane = tid & 31, wid = tid >> 5;
    int m0 = blockIdx.y * 128, n0 = blockIdx.x * 128;
    int wm = wid & 1, wn = wid >> 1;     // 2 x 4 warp grid: warp tile 64(M) x 32(N)

    int nst = K >> 5;                     // BK = 32

    // cp.async mapping: chunk c (0..511 per tensor): row = c>>2, seg = c&3
    int c0r = tid >> 1;                  // unused; explicit below
    (void)c0r;

    float acc[16][4];
    #pragma unroll
    for (int i = 0; i < 16; i++)
        #pragma unroll
        for (int j = 0; j < 4; j++) acc[i][j] = 0.f;

    // per-lane ldmatrix row offset (16 rows x 80B, two 16B halves)
    uint32_t rowoff = (uint32_t)((lane & 15) * 80 + (lane >> 4) * 16);

    // -------- issue cp.async for one stage --------
    auto issue = [&](int s, int buf) {
        uint32_t dst = sb + buf * GSTG;
        int k0 = s << 5;
        #pragma unroll
        for (int it = 0; it < 2; it++) {
            int c = tid + it * 256;      // 0..511
            int row = c >> 2, seg = c & 3;
            uint32_t doff = (uint32_t)(row * 80 + seg * 16);
            size_t aoff = (size_t)(m0 + row) * K + k0 + seg * 8;
            size_t boff = (size_t)(n0 + row) * K + k0 + seg * 8;
            cp16(dst + SA_H + doff, Ah + aoff);
            cp16(dst + SA_L + doff, Al + aoff);
            cp16(dst + SB_H + doff, Bh + boff);
            cp16(dst + SB_L + doff, Bl + boff);
        }
    };

    issue(0, 0);
    CP_COMMIT();

    for (int s = 0; s < nst; s++) {
        int buf = s & 1;
        if (s + 1 < nst) {
            issue(s + 1, buf ^ 1);
            CP_COMMIT();
            CP_WAIT(1);
        } else {
            CP_WAIT(0);
        }
        __syncthreads();

        uint32_t base = sb + buf * GSTG;
        uint32_t abase = base + (uint32_t)(wm * 64 * 80) + rowoff;
        uint32_t bbase = base + SB_H + (uint32_t)(wn * 32 * 80) + rowoff;

        #pragma unroll
        for (int kst = 0; kst < 2; kst++) {
            uint32_t koff = (uint32_t)(kst * 32);
            uint32_t ah[4][4], al[4][4], bh[2][4], bl[2][4];
            #pragma unroll
            for (int mt = 0; mt < 4; mt++) {
                ldsm4(ah[mt], abase + SA_H + mt * (16 * 80) + koff);
                ldsm4(al[mt], abase + SA_L + mt * (16 * 80) + koff);
            }
            ldsm4(bh[0], bbase + koff);
            ldsm4(bh[1], bbase + (16 * 80) + koff);
            ldsm4(bl[0], bbase + (SB_L - SB_H) + koff);
            ldsm4(bl[1], bbase + (SB_L - SB_H) + (16 * 80) + koff);

            #pragma unroll
            for (int mt = 0; mt < 4; mt++) {
                #pragma unroll
                for (int nt = 0; nt < 4; nt++) {
                    uint32_t b0h = bh[nt >> 1][nt & 1];
                    uint32_t b1h = bh[nt >> 1][(nt & 1) + 2];
                    uint32_t b0l = bl[nt >> 1][nt & 1];
                    uint32_t b1l = bl[nt >> 1][(nt & 1) + 2];
                    float* c = acc[mt * 4 + nt];
                    mma_bf16(c, ah[mt], b0h, b1h);   // hi*hi
                    mma_bf16(c, al[mt], b0h, b1h);   // lo*hi
                    mma_bf16(c, ah[mt], b0l, b1l);   // hi*lo
                }
            }
        }
        __syncthreads();
    }

    // -------- epilogue --------
    int mrow = m0 + wm * 64 + (lane >> 2);
    int ncol = n0 + wn * 32 + (lane & 3) * 2;
    #pragma unroll
    for (int mt = 0; mt < 4; mt++) {
        #pragma unroll
        for (int nt = 0; nt < 4; nt++) {
            float* a = acc[mt * 4 + nt];
            int nn = ncol + nt * 8;
            float b0 = bias[nn], b1 = bias[nn + 1];
            int r0 = mrow + mt * 16;
            int r1 = r0 + 8;
            float x0 = a[0] + b0, x1 = a[1] + b1;
            float y0 = a[2] + b0, y1 = a[3] + b1;
            if (epi == 1 || epi == 3) {
                x0 = x0 / (1.f + expf(-x0));
                x1 = x1 / (1.f + expf(-x1));
                y0 = y0 / (1.f + expf(-y0));
                y1 = y1 / (1.f + expf(-y1));
            }
            if (epi == 3) {
                __nv_bfloat162 h0 = __floats2bfloat162_rn(x0, x1);
                __nv_bfloat162 h1 = __floats2bfloat162_rn(y0, y1);
                float2 f0 = __bfloat1622float2(h0);
                float2 f1 = __bfloat1622float2(h1);
                __nv_bfloat162 l0 = __floats2bfloat162_rn(x0 - f0.x, x1 - f0.y);
                __nv_bfloat162 l1 = __floats2bfloat162_rn(y0 - f1.x, y1 - f1.y);
                *(__nv_bfloat162*)(Ch + (size_t)r0 * N + nn) = h0;
                *(__nv_bfloat162*)(Cl + (size_t)r0 * N + nn) = l0;
                *(__nv_bfloat162*)(Ch + (size_t)r1 * N + nn) = h1;
                *(__nv_bfloat162*)(Cl + (size_t)r1 * N + nn) = l1;
            } else {
                float* p0 = C + (size_t)r0 * N + nn;
                float* p1 = C + (size_t)r1 * N + nn;
                if (epi == 2) {
                    float2 c0 = *(float2*)p0;
                    float2 c1 = *(float2*)p1;
                    x0 += c0.x; x1 += c0.y;
                    y0 += c1.x; y1 += c1.y;
                }
                *(float2*)p0 = make_float2(x0, x1);
                *(float2*)p1 = make_float2(y0, y1);
            }
        }
    }
}

// ---------------- chunkwise retention: one CTA per (b, head) -----------
__global__ void retention_kernel(const float* __restrict__ q,
                                 const float* __restrict__ k,
                                 const float* __restrict__ v,
                                 float* __restrict__ ret)
{
    extern __shared__ float smf[];
    float* sq    = smf;                      // 68*64
    float* sk    = sq + CHK * DH;
    float* sv    = sk + CHK * DH;
    float* st    = sv + CHK * DH;            // 64*64
    float* inner = st + DH * DH;             // 68*68
    __shared__ float gpow[CHK + 1];

    int bh = blockIdx.x;
    int b  = bh >> 3;
    int hh = bh & 7;
    int tid = threadIdx.x;
    float gamma = 1.f - exp2f(-5.f - (float)hh);
    if (tid <= CHK) gpow[tid] = powf(gamma, (float)tid);
    for (int i = tid; i < DH * DH; i += 256) st[i] = 0.f;
    __syncthreads();
    float chunk_dec = gpow[CHK];

    for (int c = 0; c < NCHUNK; c++) {
        int base = ((b * SS + c * CHK) * HH + hh) * DH;
        for (int i = tid; i < CHK * DH; i += 256) {
            int r = i >> 6, d = i & 63;
            int g = base + r * DD + d;
            sq[i] = q[g];
            sk[i] = k[g];
            sv[i] = v[g];
        }
        __syncthreads();

        for (int e = tid; e < CHK * CHK; e += 256) {
            int i = e / CHK, j = e - i * CHK;
            float s = 0.f;
            if (i >= j) {
                const float4* qi = (const float4*)(sq + i * DH);
                const float4* kj = (const float4*)(sk + j * DH);
                #pragma unroll
                for (int d = 0; d < 16; d++) {
                    float4 a = qi[d], bb = kj[d];
                    s += a.x*bb.x + a.y*bb.y + a.z*bb.z + a.w*bb.w;
                }
                s *= gpow[i - j];
            }
            inner[e] = s;
        }
        __syncthreads();

        for (int e = tid; e < CHK * 16; e += 256) {
            int i = e >> 4, d4 = (e & 15) << 2;
            float4 acc = make_float4(0.f, 0.f, 0.f, 0.f);
            const float* in_i = inner + i * CHK;
            for (int j = 0; j <= i; j++) {
                float w = in_i[j];
                float4 vv = *(const float4*)(sv + j * DH + d4);
                acc.x += w * vv.x; acc.y += w * vv.y;
                acc.z += w * vv.z; acc.w += w * vv.w;
            }
            float4 a2 = make_float4(0.f, 0.f, 0.f, 0.f);
            const float* qi = sq + i * DH;
            #pragma unroll 8
            for (int ee = 0; ee < DH; ee++) {
                float qv = qi[ee];
                float4 sr = *(const float4*)(st + ee * DH + d4);
                a2.x += qv * sr.x; a2.y += qv * sr.y;
                a2.z += qv * sr.z; a2.w += qv * sr.w;
            }
            float cd = gamma * gpow[i];
            acc.x += a2.x * cd; acc.y += a2.y * cd;
            acc.z += a2.z * cd; acc.w += a2.w * cd;
            *(float4*)(&ret[base + i * DD + d4]) = acc;
        }
        __syncthreads();

        for (int e = tid; e < DH * 16; e += 256) {
            int d = e >> 4, e4 = (e & 15) << 2;
            float4 s = *(const float4*)(st + d * DH + e4);
            s.x *= chunk_dec; s.y *= chunk_dec; s.z *= chunk_dec; s.w *= chunk_dec;
            for (int j = 0; j < CHK; j++) {
                float kv = sk[j * DH + d] * gpow[CHK - 1 - j];
                float4 vv = *(const float4*)(sv + j * DH + e4);
                s.x += kv * vv.x; s.y += kv * vv.y;
                s.z += kv * vv.z; s.w += kv * vv.w;
            }
            *(float4*)(st + d * DH + e4) = s;
        }
        __syncthreads();
    }
}

// ------- per-head group norm fused with gate -> bf16 hi/lo split -------
__global__ void gnorm_gate_kernel(const float* __restrict__ ret,
                                  const float* __restrict__ gnw,
                                  const float* __restrict__ gnb,
                                  const float* __restrict__ gate,
                                  __nv_bfloat16* __restrict__ ghi,
                                  __nv_bfloat16* __restrict__ glo)
{
    int grp  = blockIdx.x;
    int hh   = grp & 7;
    int base = (grp >> 3) * DD + hh * DH;
    int lane = threadIdx.x;
    float v0 = ret[base + lane], v1 = ret[base + lane + 32];
    float s = v0 + v1, ss = v0 * v0 + v1 * v1;
    #pragma unroll
    for (int o = 16; o; o >>= 1) {
        s  += __shfl_xor_sync(0xffffffffu, s,  o);
        ss += __shfl_xor_sync(0xffffffffu, ss, o);
    }
    float mean = s * (1.f / DH);
    float var  = ss * (1.f / DH) - mean * mean;
    float rstd = rsqrtf(var + EPS);
    int wi = hh * DH + lane;
    float o0 = (v0 - mean) * rstd * gnw[wi]      + gnb[wi];
    float o1 = (v1 - mean) * rstd * gnw[wi + 32] + gnb[wi + 32];
    float p0 = gate[base + lane]      * o0;
    float p1 = gate[base + lane + 32] * o1;
    __nv_bfloat16 h0 = __float2bfloat16(p0);
    __nv_bfloat16 h1 = __float2bfloat16(p1);
    ghi[base + lane]      = h0;
    ghi[base + lane + 32] = h1;
    glo[base + lane]      = __float2bfloat16(p0 - __bfloat162float(h0));
    glo[base + lane + 32] = __float2bfloat16(p1 - __bfloat162float(h1));
}

// ---------------- host orchestration ----------------
extern "C" void kernel_launch(void* const* d_in, const int* in_sizes, int n_in,
                              void* d_out, int out_size)
{
    const int*   tokens = (const int*)  d_in[0];
    const float* emb    = (const float*)d_in[1];
    const float* Wq = (const float*)d_in[2],  * bq = (const float*)d_in[3];
    const float* Wk = (const float*)d_in[4],  * bk = (const float*)d_in[5];
    const float* Wv = (const float*)d_in[6],  * bv = (const float*)d_in[7];
    const float* Wg = (const float*)d_in[8],  * bg = (const float*)d_in[9];
    const float* Wo = (const float*)d_in[10], * bo = (const float*)d_in[11];
    const float* gnw  = (const float*)d_in[12], * gnb  = (const float*)d_in[13];
    const float* ln1w = (const float*)d_in[14], * ln1b = (const float*)d_in[15];
    const float* ln2w = (const float*)d_in[16], * ln2b = (const float*)d_in[17];
    const float* w1 = (const float*)d_in[18], * b1 = (const float*)d_in[19];
    const float* w2 = (const float*)d_in[20], * b2 = (const float*)d_in[21];

    float* x = (float*)d_out;

    float* fb = nullptr;
    cudaGetSymbolAddress((void**)&fb, g_scratch);
    const size_t SZ = (size_t)MROWS * DD;
    float* q    = fb;
    float* k    = fb + SZ;
    float* v    = fb + 2 * SZ;
    float* gate = fb + 3 * SZ;
    float* ret  = fb + 4 * SZ;

    __nv_bfloat16* ab = nullptr;
    cudaGetSymbolAddress((void**)&ab, g_act);
    __nv_bfloat16* h_hi  = ab;
    __nv_bfloat16* h_lo  = ab + SZ;
    __nv_bfloat16* g_hi  = ab + 2 * SZ;
    __nv_bfloat16* g_lo  = ab + 3 * SZ;
    __nv_bfloat16* ff_hi = ab + 4 * SZ;          // MROWS*FFN = 4*SZ
    __nv_bfloat16* ff_lo = ab + 8 * SZ;

    __nv_bfloat16* wts = nullptr;
    cudaGetSymbolAddress((void**)&wts, g_wts);
    __nv_bfloat16* wq_h = wts;
    __nv_bfloat16* wq_l = wts + 1 * W5;
    __nv_bfloat16* wk_h = wts + 2 * W5;
    __nv_bfloat16* wk_l = wts + 3 * W5;
    __nv_bfloat16* wv_h = wts + 4 * W5;
    __nv_bfloat16* wv_l = wts + 5 * W5;
    __nv_bfloat16* wg_h = wts + 6 * W5;
    __nv_bfloat16* wg_l = wts + 7 * W5;
    __nv_bfloat16* wo_h = wts + 8 * W5;
    __nv_bfloat16* wo_l = wts + 9 * W5;
    __nv_bfloat16* w1_h = wts + 10 * W5;
    __nv_bfloat16* w1_l = wts + 10 * W5 + WF;
    __nv_bfloat16* w2_h = wts + 10 * W5 + 2 * WF;
    __nv_bfloat16* w2_l = wts + 10 * W5 + 3 * WF;

    const int RET_SMEM = (3 * CHK * DH + DH * DH + CHK * CHK) * (int)sizeof(float);
    cudaFuncSetAttribute(retention_kernel,
                         cudaFuncAttributeMaxDynamicSharedMemorySize, RET_SMEM);
    cudaFuncSetAttribute(tc_gemm,
                         cudaFuncAttributeMaxDynamicSharedMemorySize, GEMM_SMEM);

    // ---- weight transpose + bf16 split ----
    dim3 wb(32, 8);
    dim3 gDD(DD / 32, DD / 32, LL);
    dim3 gF1(FFN / 32, DD / 32, LL);
    dim3 gF2(DD / 32, FFN / 32, LL);
    wconv_kernel<<<gDD, wb>>>(Wq, wq_h, wq_l, DD, DD);
    wconv_kernel<<<gDD, wb>>>(Wk, wk_h, wk_l, DD, DD);
    wconv_kernel<<<gDD, wb>>>(Wv, wv_h, wv_l, DD, DD);
    wconv_kernel<<<gDD, wb>>>(Wg, wg_h, wg_l, DD, DD);
    wconv_kernel<<<gDD, wb>>>(Wo, wo_h, wo_l, DD, DD);
    wconv_kernel<<<gF1, wb>>>(w1, w1_h, w1_l, DD, FFN);
    wconv_kernel<<<gF2, wb>>>(w2, w2_h, w2_l, FFN, DD);

    dim3 gemmD(DD / 128, MROWS / 128);   // (4, 51)
    dim3 gemmF(FFN / 128, MROWS / 128);  // (16, 51)
    int rotTotal = MROWS * HH * 32;
    int rotBlocks = (rotTotal + 255) / 256;

    embed_kernel<<<MROWS, 256>>>(tokens, emb, x);

    for (int l = 0; l < LL; l++) {
        const size_t oW  = (size_t)l * DD * DD;
        const size_t oF  = (size_t)l * DD * FFN;
        const size_t ob  = (size_t)l * DD;
        const size_t obf = (size_t)l * FFN;

        layernorm_split_kernel<<<MROWS, 256>>>(x, ln1w + ob, ln1b + ob, h_hi, h_lo);

        tc_gemm<<<gemmD, 256, GEMM_SMEM>>>(h_hi, h_lo, wq_h + oW, wq_l + oW,
                                           bq + ob, q, nullptr, nullptr, DD, DD, 0);
        tc_gemm<<<gemmD, 256, GEMM_SMEM>>>(h_hi, h_lo, wk_h + oW, wk_l + oW,
                                           bk + ob, k, nullptr, nullptr, DD, DD, 0);
        tc_gemm<<<gemmD, 256, GEMM_SMEM>>>(h_hi, h_lo, wv_h + oW, wv_l + oW,
                                           bv + ob, v, nullptr, nullptr, DD, DD, 0);
        tc_gemm<<<gemmD, 256, GEMM_SMEM>>>(h_hi, h_lo, wg_h + oW, wg_l + oW,
                                           bg + ob, gate, nullptr, nullptr, DD, DD, 1);

        rotary_kernel<<<rotBlocks, 256>>>(q, 1.f, rotTotal);
        rotary_kernel<<<rotBlocks, 256>>>(k, 0.125f, rotTotal);

        retention_kernel<<<BB * HH, 256, RET_SMEM>>>(q, k, v, ret);

        gnorm_gate_kernel<<<MROWS * HH, 32>>>(ret, gnw + ob, gnb + ob, gate, g_hi, g_lo);

        tc_gemm<<<gemmD, 256, GEMM_SMEM>>>(g_hi, g_lo, wo_h + oW, wo_l + oW,
                                           bo + ob, x, nullptr, nullptr, DD, DD, 2);

        layernorm_split_kernel<<<MROWS, 256>>>(x, ln2w + ob, ln2b + ob, h_hi, h_lo);

        tc_gemm<<<gemmF, 256, GEMM_SMEM>>>(h_hi, h_lo, w1_h + oF, w1_l + oF,
                                           b1 + obf, nullptr, ff_hi, ff_lo, DD, FFN, 3);
        tc_gemm<<<gemmD, 256, GEMM_SMEM>>>(ff_hi, ff_lo, w2_h + oF, w2_l + oF,
                                           b2 + ob, x, nullptr, nullptr, FFN, DD, 2);
    }
}

// round 4
// speedup vs baseline: 2.4273x; 1.2920x over previous
#include <cuda_runtime.h>
#include <cuda_bf16.h>
#include <math.h>
#include <stdint.h>

// ---------------- problem constants ----------------
#define BB   16
#define SS   408
#define DD   512
#define LL   10
#define FFN  2048
#define HH   8
#define DH   64
#define CHK  68
#define NCHUNK (SS/CHK)     // 6
#define MROWS (BB*SS)       // 6528
#define EPS  1e-5f

// ---------------- scratch (no allocations allowed) ----------------
// fp32: q, k, v, gate (consecutive!), ret
__device__ __align__(16) float g_scratch[(size_t)5 * MROWS * DD];
// bf16 activations hi/lo: h(2) + g(2) + ff(8) in units of MROWS*DD
__device__ __align__(16) __nv_bfloat16 g_act[(size_t)12 * MROWS * DD];
// bf16 hi/lo pre-transposed weights
#define W5  ((size_t)LL * DD * DD)
#define WF  ((size_t)LL * DD * FFN)
__device__ __align__(16) __nv_bfloat16 g_wts[10 * W5 + 4 * WF];
// packed qkvg bias [L][2048]
__device__ __align__(16) float g_bias[(size_t)LL * 2048];

// ================= PTX helpers (family-portable: sm_80+) =================
__device__ __forceinline__ uint32_t smem_u32(const void* p) {
    uint32_t a;
    asm("{ .reg .u64 t; cvta.to.shared.u64 t, %1; cvt.u32.u64 %0, t; }"
        : "=r"(a) : "l"(p));
    return a;
}
__device__ __forceinline__ void cp16(uint32_t dst, const void* src) {
    asm volatile("cp.async.cg.shared.global [%0], [%1], 16;"
                 :: "r"(dst), "l"(src));
}
#define CP_COMMIT() asm volatile("cp.async.commit_group;" ::: "memory")
#define CP_WAIT(n)  asm volatile("cp.async.wait_group %0;" :: "n"(n) : "memory")

__device__ __forceinline__ void ldsm4(uint32_t* r, uint32_t addr) {
    asm volatile("ldmatrix.sync.aligned.m8n8.x4.shared.b16 {%0,%1,%2,%3}, [%4];"
                 : "=r"(r[0]), "=r"(r[1]), "=r"(r[2]), "=r"(r[3]) : "r"(addr));
}
__device__ __forceinline__ void mma_bf16(float* c, const uint32_t* a,
                                         uint32_t b0, uint32_t b1) {
    asm volatile(
        "mma.sync.aligned.m16n8k16.row.col.f32.bf16.bf16.f32 "
        "{%0,%1,%2,%3}, {%4,%5,%6,%7}, {%8,%9}, {%0,%1,%2,%3};"
        : "+f"(c[0]), "+f"(c[1]), "+f"(c[2]), "+f"(c[3])
        : "r"(a[0]), "r"(a[1]), "r"(a[2]), "r"(a[3]), "r"(b0), "r"(b1));
}

// ---------------- embedding gather + qkvg bias pack ----------------
__global__ void embed_kernel(const int* __restrict__ tokens,
                             const float* __restrict__ emb,
                             float* __restrict__ x,
                             const float* __restrict__ bq,
                             const float* __restrict__ bk,
                             const float* __restrict__ bv,
                             const float* __restrict__ bg,
                             float* __restrict__ biasPacked)
{
    int row = blockIdx.x;
    int tok = tokens[row];
    const float2* src = (const float2*)(emb + (size_t)tok * DD);
    float2* dst = (float2*)(x + (size_t)row * DD);
    dst[threadIdx.x] = src[threadIdx.x];
    if (blockIdx.x < (LL * 2048) / 512) {
        #pragma unroll
        for (int t = 0; t < 2; t++) {
            int gi = blockIdx.x * 512 + threadIdx.x + t * 256;
            int l = gi >> 11, r = gi & 2047;
            int w = r >> 9, d = r & 511;
            const float* s = (w == 0) ? bq : (w == 1) ? bk : (w == 2) ? bv : bg;
            biasPacked[gi] = s[l * 512 + d];
        }
    }
}

// ---------------- layer norm -> bf16 hi/lo split ----------------
__global__ void layernorm_split_kernel(const float* __restrict__ x,
                                       const float* __restrict__ w,
                                       const float* __restrict__ b,
                                       __nv_bfloat16* __restrict__ hi,
                                       __nv_bfloat16* __restrict__ lo)
{
    int row = blockIdx.x;
    int tid = threadIdx.x;                 // 256
    const float* xr = x + (size_t)row * DD;
    float v0 = xr[tid], v1 = xr[tid + 256];
    float s = v0 + v1, ss = v0*v0 + v1*v1;
    __shared__ float rs[8], rss[8];
    #pragma unroll
    for (int o = 16; o; o >>= 1) {
        s  += __shfl_xor_sync(0xffffffffu, s,  o);
        ss += __shfl_xor_sync(0xffffffffu, ss, o);
    }
    if ((tid & 31) == 0) { rs[tid >> 5] = s; rss[tid >> 5] = ss; }
    __syncthreads();
    float tot = 0.f, tots = 0.f;
    #pragma unroll
    for (int i = 0; i < 8; i++) { tot += rs[i]; tots += rss[i]; }
    float mean = tot * (1.f / DD);
    float var  = tots * (1.f / DD) - mean * mean;
    float rstd = rsqrtf(var + EPS);
    float o0 = (v0 - mean) * rstd * w[tid]       + b[tid];
    float o1 = (v1 - mean) * rstd * w[tid + 256] + b[tid + 256];
    size_t base = (size_t)row * DD;
    __nv_bfloat16 h0 = __float2bfloat16(o0);
    __nv_bfloat16 h1 = __float2bfloat16(o1);
    hi[base + tid]       = h0;
    hi[base + tid + 256] = h1;
    lo[base + tid]       = __float2bfloat16(o0 - __bfloat162float(h0));
    lo[base + tid + 256] = __float2bfloat16(o1 - __bfloat162float(h1));
}

// ---------------- rotary for q and k fused ----------------
__global__ void rotary_qk_kernel(float* __restrict__ q, float* __restrict__ k,
                                 int total)
{
    int idx = blockIdx.x * blockDim.x + threadIdx.x;
    if (idx >= total) return;
    int j   = idx & 31;
    int hh  = (idx >> 5) & 7;
    int row = idx >> 8;
    int s   = row % SS;
    float inv = powf(10000.f, -2.f * (float)j / 64.f);
    float ang = (float)s * inv;
    float sn, cs;
    sincosf(ang, &sn, &cs);
    int base = row * DD + hh * DH + j;
    float t1 = q[base], t2 = q[base + 32];
    q[base]      = t1 * cs - t2 * sn;
    q[base + 32] = t2 * cs + t1 * sn;
    t1 = k[base]; t2 = k[base + 32];
    k[base]      = (t1 * cs - t2 * sn) * 0.125f;
    k[base + 32] = (t2 * cs + t1 * sn) * 0.125f;
}

// ------- weight transpose + bf16 hi/lo split: 5 square mats fused -------
// grid (16,16, 5*LL): z = m*LL + l; m: 0..3 -> qkvg combined (roff m*512), 4 -> Wo
__global__ void wconv5_kernel(const float* __restrict__ Wq, const float* __restrict__ Wk,
                              const float* __restrict__ Wv, const float* __restrict__ Wg,
                              const float* __restrict__ Wo,
                              __nv_bfloat16* __restrict__ qkvg_h, __nv_bfloat16* __restrict__ qkvg_l,
                              __nv_bfloat16* __restrict__ wo_h,   __nv_bfloat16* __restrict__ wo_l)
{
    __shared__ float t[32][33];
    int z = blockIdx.z;
    int m = z / LL, l = z - m * LL;
    const float* S = (m == 0) ? Wq : (m == 1) ? Wk : (m == 2) ? Wv : (m == 3) ? Wg : Wo;
    const float* s = S + (size_t)l * DD * DD;
    int n0 = blockIdx.x * 32, k0 = blockIdx.y * 32;
    int tx = threadIdx.x, ty = threadIdx.y;
    #pragma unroll
    for (int r = ty; r < 32; r += 8)
        t[r][tx] = s[(size_t)(k0 + r) * DD + n0 + tx];
    __syncthreads();
    __nv_bfloat16* hi;
    __nv_bfloat16* lo;
    size_t dbase;
    if (m < 4) {
        hi = qkvg_h; lo = qkvg_l;
        dbase = (size_t)l * 2048 * DD + (size_t)m * 512 * DD;
    } else {
        hi = wo_h; lo = wo_l;
        dbase = (size_t)l * DD * DD;
    }
    #pragma unroll
    for (int r = ty; r < 32; r += 8) {
        float x = t[tx][r];              // element (k0+tx, n0+r)
        __nv_bfloat16 h = __float2bfloat16(x);
        float rem = x - __bfloat162float(h);
        size_t o = dbase + (size_t)(n0 + r) * DD + k0 + tx;
        hi[o] = h;
        lo[o] = __float2bfloat16(rem);
    }
}

// ---------------- generic weight transpose (ff mats) --------------
__global__ void wconv_kernel(const float* __restrict__ src,
                             __nv_bfloat16* __restrict__ hi,
                             __nv_bfloat16* __restrict__ lo,
                             int K, int N)
{
    __shared__ float t[32][33];
    int n0 = blockIdx.x * 32, k0 = blockIdx.y * 32;
    const float* s = src + (size_t)blockIdx.z * K * N;
    int tx = threadIdx.x, ty = threadIdx.y;
    #pragma unroll
    for (int r = ty; r < 32; r += 8)
        t[r][tx] = s[(size_t)(k0 + r) * N + n0 + tx];
    __syncthreads();
    size_t dbase = (size_t)blockIdx.z * N * K;
    #pragma unroll
    for (int r = ty; r < 32; r += 8) {
        float x = t[tx][r];
        __nv_bfloat16 h = __float2bfloat16(x);
        float rem = x - __bfloat162float(h);
        size_t o = dbase + (size_t)(n0 + r) * K + k0 + tx;
        hi[o] = h;
        lo[o] = __float2bfloat16(rem);
    }
}

// ---------------- tensor-core GEMM (bf16 3-term, BM=192 BK=64) ----------
// A hi/lo: [M][K] bf16 row-major. B hi/lo: [N][K] bf16 K-major.
// epi: 1 silu fp32 / 2 add-to-C fp32 / 3 silu->bf16 split / 4 fused qkvg
#define APITCH 144
#define SA_H 0
#define SA_L 27648
#define SB_H 55296
#define SB_L 73728
#define GSTG 92160
#define GEMM_SMEM (2 * GSTG)

__global__ void __launch_bounds__(256, 1)
tc_gemm(const __nv_bfloat16* __restrict__ Ah,
        const __nv_bfloat16* __restrict__ Al,
        const __nv_bfloat16* __restrict__ Bh,
        const __nv_bfloat16* __restrict__ Bl,
        const float* __restrict__ bias,
        float* __restrict__ C,
        __nv_bfloat16* __restrict__ Ch,
        __nv_bfloat16* __restrict__ Cl,
        int K, int N, int epi)
{
    extern __shared__ char sm[];
    uint32_t sb = smem_u32(sm);
    int tid = threadIdx.x;
    int lane = tid & 31, wid = tid >> 5;
    int m0 = blockIdx.y * 192, n0 = blockIdx.x * 128;
    int wm = wid & 1, wn = wid >> 1;      // warp tile 96(M) x 32(N)

    int nst = K >> 6;                      // BK = 64

    float acc[24][4];
    #pragma unroll
    for (int i = 0; i < 24; i++)
        #pragma unroll
        for (int j = 0; j < 4; j++) acc[i][j] = 0.f;

    uint32_t rowoff = (uint32_t)((lane & 15) * APITCH + (lane >> 4) * 16);

    auto issue = [&](int s, int buf) {
        uint32_t dst = sb + buf * GSTG;
        int k0 = s << 6;
        #pragma unroll
        for (int it = 0; it < 6; it++) {
            int c = tid + it * 256;          // 0..1535
            int row = c >> 3, seg = c & 7;
            uint32_t doff = (uint32_t)(row * APITCH + seg * 16);
            size_t aoff = (size_t)(m0 + row) * K + k0 + seg * 8;
            cp16(dst + SA_H + doff, Ah + aoff);
            cp16(dst + SA_L + doff, Al + aoff);
        }
        #pragma unroll
        for (int it = 0; it < 4; it++) {
            int c = tid + it * 256;          // 0..1023
            int row = c >> 3, seg = c & 7;
            uint32_t doff = (uint32_t)(row * APITCH + seg * 16);
            size_t boff = (size_t)(n0 + row) * K + k0 + seg * 8;
            cp16(dst + SB_H + doff, Bh + boff);
            cp16(dst + SB_L + doff, Bl + boff);
        }
    };

    issue(0, 0);
    CP_COMMIT();

    for (int s = 0; s < nst; s++) {
        int buf = s & 1;
        if (s + 1 < nst) {
            issue(s + 1, buf ^ 1);
            CP_COMMIT();
            CP_WAIT(1);
        } else {
            CP_WAIT(0);
        }
        __syncthreads();

        uint32_t base  = sb + buf * GSTG;
        uint32_t abase = base + (uint32_t)(wm * 96 * APITCH) + rowoff;
        uint32_t bbase = base + SB_H + (uint32_t)(wn * 32 * APITCH) + rowoff;

        #pragma unroll
        for (int kst = 0; kst < 4; kst++) {
            uint32_t koff = (uint32_t)(kst * 32);
            uint32_t bh[2][4], bl[2][4];
            ldsm4(bh[0], bbase + koff);
            ldsm4(bh[1], bbase + 16 * APITCH + koff);
            ldsm4(bl[0], bbase + (SB_L - SB_H) + koff);
            ldsm4(bl[1], bbase + (SB_L - SB_H) + 16 * APITCH + koff);
            #pragma unroll
            for (int mt = 0; mt < 6; mt++) {
                uint32_t ah[4], al[4];
                ldsm4(ah, abase + SA_H + mt * (16 * APITCH) + koff);
                ldsm4(al, abase + SA_L + mt * (16 * APITCH) + koff);
                #pragma unroll
                for (int nt = 0; nt < 4; nt++)
                    mma_bf16(acc[mt * 4 + nt], ah,
                             bh[nt >> 1][nt & 1], bh[nt >> 1][(nt & 1) + 2]);
                #pragma unroll
                for (int nt = 0; nt < 4; nt++)
                    mma_bf16(acc[mt * 4 + nt], al,
                             bh[nt >> 1][nt & 1], bh[nt >> 1][(nt & 1) + 2]);
                #pragma unroll
                for (int nt = 0; nt < 4; nt++)
                    mma_bf16(acc[mt * 4 + nt], ah,
                             bl[nt >> 1][nt & 1], bl[nt >> 1][(nt & 1) + 2]);
            }
        }
        __syncthreads();
    }

    // -------- epilogue --------
    bool fused = (epi == 4);
    int which = n0 >> 9;
    float* Cb = C;
    int ldc = N, ncol0 = n0;
    if (fused) {
        Cb = C + (size_t)which * ((size_t)MROWS * 512);
        ldc = 512;
        ncol0 = n0 & 511;
    }
    bool dosilu = (epi == 1) || (epi == 3) || (fused && which == 3);

    int r_lane = lane >> 2;
    int c_lane = (lane & 3) * 2;
    #pragma unroll
    for (int mt = 0; mt < 6; mt++) {
        int r0 = m0 + wm * 96 + mt * 16 + r_lane;
        int r1 = r0 + 8;
        #pragma unroll
        for (int nt = 0; nt < 4; nt++) {
            float* a = acc[mt * 4 + nt];
            int ncb = wn * 32 + nt * 8 + c_lane;   // 0..127 in block
            float b0 = bias[n0 + ncb], b1 = bias[n0 + ncb + 1];
            float x0 = a[0] + b0, x1 = a[1] + b1;
            float y0 = a[2] + b0, y1 = a[3] + b1;
            if (dosilu) {
                x0 = x0 / (1.f + expf(-x0));
                x1 = x1 / (1.f + expf(-x1));
                y0 = y0 / (1.f + expf(-y0));
                y1 = y1 / (1.f + expf(-y1));
            }
            int nn = ncol0 + ncb;
            if (epi == 3) {
                __nv_bfloat162 h0 = __floats2bfloat162_rn(x0, x1);
                __nv_bfloat162 h1 = __floats2bfloat162_rn(y0, y1);
                float2 f0 = __bfloat1622float2(h0);
                float2 f1 = __bfloat1622float2(h1);
                __nv_bfloat162 l0 = __floats2bfloat162_rn(x0 - f0.x, x1 - f0.y);
                __nv_bfloat162 l1 = __floats2bfloat162_rn(y0 - f1.x, y1 - f1.y);
                *(__nv_bfloat162*)(Ch + (size_t)r0 * N + nn) = h0;
                *(__nv_bfloat162*)(Cl + (size_t)r0 * N + nn) = l0;
                *(__nv_bfloat162*)(Ch + (size_t)r1 * N + nn) = h1;
                *(__nv_bfloat162*)(Cl + (size_t)r1 * N + nn) = l1;
            } else {
                float* p0 = Cb + (size_t)r0 * ldc + nn;
                float* p1 = Cb + (size_t)r1 * ldc + nn;
                if (epi == 2) {
                    float2 c0 = *(float2*)p0;
                    float2 c1 = *(float2*)p1;
                    x0 += c0.x; x1 += c0.y;
                    y0 += c1.x; y1 += c1.y;
                }
                *(float2*)p0 = make_float2(x0, x1);
                *(float2*)p1 = make_float2(y0, y1);
            }
        }
    }
}

// ---------------- chunkwise retention: one CTA per (b, head) -----------
#define KT_PITCH 72
__global__ void retention_kernel(const float* __restrict__ q,
                                 const float* __restrict__ k,
                                 const float* __restrict__ v,
                                 float* __restrict__ ret)
{
    extern __shared__ float smf[];
    float* sq    = smf;                      // 68*64
    float* sk    = sq + CHK * DH;            // 68*64
    float* sv    = sk + CHK * DH;            // 68*64
    float* st    = sv + CHK * DH;            // 64*64
    float* inner = st + DH * DH;             // 68*68
    float* skT   = inner + CHK * CHK;        // 64*72 transposed k
    __shared__ float gpow[CHK + 1];

    int bh = blockIdx.x;
    int b  = bh >> 3;
    int hh = bh & 7;
    int tid = threadIdx.x;
    float gamma = 1.f - exp2f(-5.f - (float)hh);
    if (tid <= CHK) gpow[tid] = powf(gamma, (float)tid);
    for (int i = tid; i < DH * DH; i += 256) st[i] = 0.f;
    __syncthreads();
    float chunk_dec = gpow[CHK];

    for (int c = 0; c < NCHUNK; c++) {
        int base = ((b * SS + c * CHK) * HH + hh) * DH;
        for (int i = tid; i < CHK * DH; i += 256) {
            int r = i >> 6, d = i & 63;
            int g = base + r * DD + d;
            sq[i] = q[g];
            float kv = k[g];
            sk[i] = kv;
            skT[d * KT_PITCH + r] = kv;
            sv[i] = v[g];
        }
        __syncthreads();

        // inner[i][j] = (q_i . k_j) * gamma^(i-j)  via transposed k (conflict-free)
        for (int e = tid; e < CHK * 17; e += 256) {
            int i = e / 17, jg = e - i * 17;
            int j0 = jg * 4;
            float4 s = make_float4(0.f, 0.f, 0.f, 0.f);
            if (i >= j0) {
                const float* qi = sq + i * DH;
                #pragma unroll 4
                for (int d4 = 0; d4 < DH; d4 += 4) {
                    float4 qv = *(const float4*)(qi + d4);
                    float4 k0 = *(const float4*)(skT + (d4 + 0) * KT_PITCH + j0);
                    float4 k1 = *(const float4*)(skT + (d4 + 1) * KT_PITCH + j0);
                    float4 k2 = *(const float4*)(skT + (d4 + 2) * KT_PITCH + j0);
                    float4 k3 = *(const float4*)(skT + (d4 + 3) * KT_PITCH + j0);
                    s.x += qv.x*k0.x + qv.y*k1.x + qv.z*k2.x + qv.w*k3.x;
                    s.y += qv.x*k0.y + qv.y*k1.y + qv.z*k2.y + qv.w*k3.y;
                    s.z += qv.x*k0.z + qv.y*k1.z + qv.z*k2.z + qv.w*k3.z;
                    s.w += qv.x*k0.w + qv.y*k1.w + qv.z*k2.w + qv.w*k3.w;
                }
            }
            float* out = inner + i * CHK + j0;
            out[0] = (i >= j0)     ? s.x * gpow[i - j0]     : 0.f;
            out[1] = (i >= j0 + 1) ? s.y * gpow[i - j0 - 1] : 0.f;
            out[2] = (i >= j0 + 2) ? s.z * gpow[i - j0 - 2] : 0.f;
            out[3] = (i >= j0 + 3) ? s.w * gpow[i - j0 - 3] : 0.f;
        }
        __syncthreads();

        for (int e = tid; e < CHK * 16; e += 256) {
            int i = e >> 4, d4 = (e & 15) << 2;
            float4 acc = make_float4(0.f, 0.f, 0.f, 0.f);
            const float* in_i = inner + i * CHK;
            for (int j = 0; j <= i; j++) {
                float w = in_i[j];
                float4 vv = *(const float4*)(sv + j * DH + d4);
                acc.x += w * vv.x; acc.y += w * vv.y;
                acc.z += w * vv.z; acc.w += w * vv.w;
            }
            float4 a2 = make_float4(0.f, 0.f, 0.f, 0.f);
            const float* qi = sq + i * DH;
            #pragma unroll 8
            for (int ee = 0; ee < DH; ee++) {
                float qv = qi[ee];
                float4 sr = *(const float4*)(st + ee * DH + d4);
                a2.x += qv * sr.x; a2.y += qv * sr.y;
                a2.z += qv * sr.z; a2.w += qv * sr.w;
            }
            float cd = gamma * gpow[i];
            acc.x += a2.x * cd; acc.y += a2.y * cd;
            acc.z += a2.z * cd; acc.w += a2.w * cd;
            *(float4*)(&ret[base + i * DD + d4]) = acc;
        }
        __syncthreads();

        for (int e = tid; e < DH * 16; e += 256) {
            int d = e >> 4, e4 = (e & 15) << 2;
            float4 s = *(const float4*)(st + d * DH + e4);
            s.x *= chunk_dec; s.y *= chunk_dec; s.z *= chunk_dec; s.w *= chunk_dec;
            for (int j = 0; j < CHK; j++) {
                float kv = sk[j * DH + d] * gpow[CHK - 1 - j];
                float4 vv = *(const float4*)(sv + j * DH + e4);
                s.x += kv * vv.x; s.y += kv * vv.y;
                s.z += kv * vv.z; s.w += kv * vv.w;
            }
            *(float4*)(st + d * DH + e4) = s;
        }
        __syncthreads();
    }
}

// ------- per-head group norm fused with gate -> bf16 hi/lo split -------
__global__ void gnorm_gate_kernel(const float* __restrict__ ret,
                                  const float* __restrict__ gnw,
                                  const float* __restrict__ gnb,
                                  const float* __restrict__ gate,
                                  __nv_bfloat16* __restrict__ ghi,
                                  __nv_bfloat16* __restrict__ glo)
{
    int grp  = blockIdx.x;
    int hh   = grp & 7;
    int base = (grp >> 3) * DD + hh * DH;
    int lane = threadIdx.x;
    float v0 = ret[base + lane], v1 = ret[base + lane + 32];
    float s = v0 + v1, ss = v0 * v0 + v1 * v1;
    #pragma unroll
    for (int o = 16; o; o >>= 1) {
        s  += __shfl_xor_sync(0xffffffffu, s,  o);
        ss += __shfl_xor_sync(0xffffffffu, ss, o);
    }
    float mean = s * (1.f / DH);
    float var  = ss * (1.f / DH) - mean * mean;
    float rstd = rsqrtf(var + EPS);
    int wi = hh * DH + lane;
    float o0 = (v0 - mean) * rstd * gnw[wi]      + gnb[wi];
    float o1 = (v1 - mean) * rstd * gnw[wi + 32] + gnb[wi + 32];
    float p0 = gate[base + lane]      * o0;
    float p1 = gate[base + lane + 32] * o1;
    __nv_bfloat16 h0 = __float2bfloat16(p0);
    __nv_bfloat16 h1 = __float2bfloat16(p1);
    ghi[base + lane]      = h0;
    ghi[base + lane + 32] = h1;
    glo[base + lane]      = __float2bfloat16(p0 - __bfloat162float(h0));
    glo[base + lane + 32] = __float2bfloat16(p1 - __bfloat162float(h1));
}

// ---------------- host orchestration ----------------
extern "C" void kernel_launch(void* const* d_in, const int* in_sizes, int n_in,
                              void* d_out, int out_size)
{
    const int*   tokens = (const int*)  d_in[0];
    const float* emb    = (const float*)d_in[1];
    const float* Wq = (const float*)d_in[2],  * bq = (const float*)d_in[3];
    const float* Wk = (const float*)d_in[4],  * bk = (const float*)d_in[5];
    const float* Wv = (const float*)d_in[6],  * bv = (const float*)d_in[7];
    const float* Wg = (const float*)d_in[8],  * bg = (const float*)d_in[9];
    const float* Wo = (const float*)d_in[10], * bo = (const float*)d_in[11];
    const float* gnw  = (const float*)d_in[12], * gnb  = (const float*)d_in[13];
    const float* ln1w = (const float*)d_in[14], * ln1b = (const float*)d_in[15];
    const float* ln2w = (const float*)d_in[16], * ln2b = (const float*)d_in[17];
    const float* w1 = (const float*)d_in[18], * b1 = (const float*)d_in[19];
    const float* w2 = (const float*)d_in[20], * b2 = (const float*)d_in[21];

    float* x = (float*)d_out;

    float* fb = nullptr;
    cudaGetSymbolAddress((void**)&fb, g_scratch);
    const size_t SZ = (size_t)MROWS * DD;
    float* q    = fb;                        // q,k,v,gate consecutive (epi4!)
    float* ret  = fb + 4 * SZ;

    __nv_bfloat16* ab = nullptr;
    cudaGetSymbolAddress((void**)&ab, g_act);
    __nv_bfloat16* h_hi  = ab;
    __nv_bfloat16* h_lo  = ab + SZ;
    __nv_bfloat16* g_hi  = ab + 2 * SZ;
    __nv_bfloat16* g_lo  = ab + 3 * SZ;
    __nv_bfloat16* ff_hi = ab + 4 * SZ;
    __nv_bfloat16* ff_lo = ab + 8 * SZ;

    __nv_bfloat16* wts = nullptr;
    cudaGetSymbolAddress((void**)&wts, g_wts);
    __nv_bfloat16* qkvg_h = wts;             // [L][2048][512]
    __nv_bfloat16* qkvg_l = wts + 4 * W5;
    __nv_bfloat16* wo_h   = wts + 8 * W5;
    __nv_bfloat16* wo_l   = wts + 9 * W5;
    __nv_bfloat16* w1_h   = wts + 10 * W5;
    __nv_bfloat16* w1_l   = wts + 10 * W5 + WF;
    __nv_bfloat16* w2_h   = wts + 10 * W5 + 2 * WF;
    __nv_bfloat16* w2_l   = wts + 10 * W5 + 3 * WF;

    float* biasP = nullptr;
    cudaGetSymbolAddress((void**)&biasP, g_bias);

    const int RET_SMEM = (3 * CHK * DH + DH * DH + CHK * CHK + DH * KT_PITCH)
                         * (int)sizeof(float);
    cudaFuncSetAttribute(retention_kernel,
                         cudaFuncAttributeMaxDynamicSharedMemorySize, RET_SMEM);
    cudaFuncSetAttribute(tc_gemm,
                         cudaFuncAttributeMaxDynamicSharedMemorySize, GEMM_SMEM);

    // launch 0: embed (+ bias pack)
    embed_kernel<<<MROWS, 256>>>(tokens, emb, x, bq, bk, bv, bg, biasP);
    // launch 1: 5 square weight mats
    dim3 wb(32, 8);
    wconv5_kernel<<<dim3(16, 16, 5 * LL), wb>>>(Wq, Wk, Wv, Wg, Wo,
                                                qkvg_h, qkvg_l, wo_h, wo_l);
    // launches 2,3: ff weights
    wconv_kernel<<<dim3(FFN / 32, DD / 32, LL), wb>>>(w1, w1_h, w1_l, DD, FFN);
    wconv_kernel<<<dim3(DD / 32, FFN / 32, LL), wb>>>(w2, w2_h, w2_l, FFN, DD);

    dim3 gemmQKVG(2048 / 128, MROWS / 192);  // (16, 34)
    dim3 gemmO(DD / 128, MROWS / 192);       // (4, 34)
    dim3 gemmF1(FFN / 128, MROWS / 192);     // (16, 34)
    dim3 gemmF2(DD / 128, MROWS / 192);      // (4, 34)
    int rotTotal = MROWS * HH * 32;
    int rotBlocks = (rotTotal + 255) / 256;

    for (int l = 0; l < LL; l++) {
        const size_t oQW = (size_t)l * 2048 * DD;
        const size_t oW  = (size_t)l * DD * DD;
        const size_t oF  = (size_t)l * DD * FFN;
        const size_t ob  = (size_t)l * DD;
        const size_t obf = (size_t)l * FFN;

        // launch 4 (l=0): ln1 ; launch 5: fused qkvg  -> profiled
        layernorm_split_kernel<<<MROWS, 256>>>(x, ln1w + ob, ln1b + ob, h_hi, h_lo);

        tc_gemm<<<gemmQKVG, 256, GEMM_SMEM>>>(h_hi, h_lo, qkvg_h + oQW, qkvg_l + oQW,
                                              biasP + (size_t)l * 2048, q,
                                              nullptr, nullptr, DD, 2048, 4);

        rotary_qk_kernel<<<rotBlocks, 256>>>(q, q + SZ, rotTotal);

        retention_kernel<<<BB * HH, 256, RET_SMEM>>>(q, q + SZ, q + 2 * SZ, ret);

        gnorm_gate_kernel<<<MROWS * HH, 32>>>(ret, gnw + ob, gnb + ob, q + 3 * SZ,
                                              g_hi, g_lo);

        tc_gemm<<<gemmO, 256, GEMM_SMEM>>>(g_hi, g_lo, wo_h + oW, wo_l + oW,
                                           bo + ob, x, nullptr, nullptr, DD, DD, 2);

        layernorm_split_kernel<<<MROWS, 256>>>(x, ln2w + ob, ln2b + ob, h_hi, h_lo);

        tc_gemm<<<gemmF1, 256, GEMM_SMEM>>>(h_hi, h_lo, w1_h + oF, w1_l + oF,
                                            b1 + obf, nullptr, ff_hi, ff_lo,
                                            DD, FFN, 3);
        tc_gemm<<<gemmF2, 256, GEMM_SMEM>>>(ff_hi, ff_lo, w2_h + oF, w2_l + oF,
                                            b2 + ob, x, nullptr, nullptr,
                                            FFN, DD, 2);
    }
}

// round 5
// speedup vs baseline: 2.4967x; 1.0286x over previous
#include <cuda_runtime.h>
#include <cuda_bf16.h>
#include <math.h>
#include <stdint.h>

// ---------------- problem constants ----------------
#define BB   16
#define SS   408
#define DD   512
#define LL   10
#define FFN  2048
#define HH   8
#define DH   64
#define CHK  68
#define NCHUNK (SS/CHK)     // 6
#define MROWS (BB*SS)       // 6528
#define EPS  1e-5f

// ---------------- scratch (no allocations allowed) ----------------
// fp32: q, k, v, gate (consecutive!), ret
__device__ __align__(16) float g_scratch[(size_t)5 * MROWS * DD];
// bf16 activations hi/lo: h(2) + g(2) + ff(8) in units of MROWS*DD
__device__ __align__(16) __nv_bfloat16 g_act[(size_t)12 * MROWS * DD];
// bf16 hi/lo pre-transposed weights
#define W5  ((size_t)LL * DD * DD)
#define WF  ((size_t)LL * DD * FFN)
__device__ __align__(16) __nv_bfloat16 g_wts[10 * W5 + 4 * WF];
// packed qkvg bias [L][2048]
__device__ __align__(16) float g_bias[(size_t)LL * 2048];
// rotary tables [S][32]
__device__ __align__(16) float g_rotcs[SS * 32];
__device__ __align__(16) float g_rotsn[SS * 32];

// ================= PTX helpers (family-portable: sm_80+) =================
__device__ __forceinline__ uint32_t smem_u32(const void* p) {
    uint32_t a;
    asm("{ .reg .u64 t; cvta.to.shared.u64 t, %1; cvt.u32.u64 %0, t; }"
        : "=r"(a) : "l"(p));
    return a;
}
__device__ __forceinline__ void cp16(uint32_t dst, const void* src) {
    asm volatile("cp.async.cg.shared.global [%0], [%1], 16;"
                 :: "r"(dst), "l"(src));
}
#define CP_COMMIT() asm volatile("cp.async.commit_group;" ::: "memory")
#define CP_WAIT(n)  asm volatile("cp.async.wait_group %0;" :: "n"(n) : "memory")

__device__ __forceinline__ void ldsm4(uint32_t* r, uint32_t addr) {
    asm volatile("ldmatrix.sync.aligned.m8n8.x4.shared.b16 {%0,%1,%2,%3}, [%4];"
                 : "=r"(r[0]), "=r"(r[1]), "=r"(r[2]), "=r"(r[3]) : "r"(addr));
}
__device__ __forceinline__ void mma_bf16(float* c, const uint32_t* a,
                                         uint32_t b0, uint32_t b1) {
    asm volatile(
        "mma.sync.aligned.m16n8k16.row.col.f32.bf16.bf16.f32 "
        "{%0,%1,%2,%3}, {%4,%5,%6,%7}, {%8,%9}, {%0,%1,%2,%3};"
        : "+f"(c[0]), "+f"(c[1]), "+f"(c[2]), "+f"(c[3])
        : "r"(a[0]), "r"(a[1]), "r"(a[2]), "r"(a[3]), "r"(b0), "r"(b1));
}

// ------- weight transpose + bf16 hi/lo split: 5 square mats fused -------
__global__ void wconv5_kernel(const float* __restrict__ Wq, const float* __restrict__ Wk,
                              const float* __restrict__ Wv, const float* __restrict__ Wg,
                              const float* __restrict__ Wo,
                              __nv_bfloat16* __restrict__ qkvg_h, __nv_bfloat16* __restrict__ qkvg_l,
                              __nv_bfloat16* __restrict__ wo_h,   __nv_bfloat16* __restrict__ wo_l)
{
    __shared__ float t[32][33];
    int z = blockIdx.z;
    int m = z / LL, l = z - m * LL;
    const float* S = (m == 0) ? Wq : (m == 1) ? Wk : (m == 2) ? Wv : (m == 3) ? Wg : Wo;
    const float* s = S + (size_t)l * DD * DD;
    int n0 = blockIdx.x * 32, k0 = blockIdx.y * 32;
    int tx = threadIdx.x, ty = threadIdx.y;
    #pragma unroll
    for (int r = ty; r < 32; r += 8)
        t[r][tx] = s[(size_t)(k0 + r) * DD + n0 + tx];
    __syncthreads();
    __nv_bfloat16* hi;
    __nv_bfloat16* lo;
    size_t dbase;
    if (m < 4) {
        hi = qkvg_h; lo = qkvg_l;
        dbase = (size_t)l * 2048 * DD + (size_t)m * 512 * DD;
    } else {
        hi = wo_h; lo = wo_l;
        dbase = (size_t)l * DD * DD;
    }
    #pragma unroll
    for (int r = ty; r < 32; r += 8) {
        float x = t[tx][r];
        __nv_bfloat16 h = __float2bfloat16(x);
        float rem = x - __bfloat162float(h);
        size_t o = dbase + (size_t)(n0 + r) * DD + k0 + tx;
        hi[o] = h;
        lo[o] = __float2bfloat16(rem);
    }
}

// ---------------- generic weight transpose (ff mats) --------------
__global__ void wconv_kernel(const float* __restrict__ src,
                             __nv_bfloat16* __restrict__ hi,
                             __nv_bfloat16* __restrict__ lo,
                             int K, int N)
{
    __shared__ float t[32][33];
    int n0 = blockIdx.x * 32, k0 = blockIdx.y * 32;
    const float* s = src + (size_t)blockIdx.z * K * N;
    int tx = threadIdx.x, ty = threadIdx.y;
    #pragma unroll
    for (int r = ty; r < 32; r += 8)
        t[r][tx] = s[(size_t)(k0 + r) * N + n0 + tx];
    __syncthreads();
    size_t dbase = (size_t)blockIdx.z * N * K;
    #pragma unroll
    for (int r = ty; r < 32; r += 8) {
        float x = t[tx][r];
        __nv_bfloat16 h = __float2bfloat16(x);
        float rem = x - __bfloat162float(h);
        size_t o = dbase + (size_t)(n0 + r) * K + k0 + tx;
        hi[o] = h;
        lo[o] = __float2bfloat16(rem);
    }
}

// ---- fused: embedding gather + LN(layer0) split + bias pack + rot tables ----
__global__ void embed_ln_kernel(const int* __restrict__ tokens,
                                const float* __restrict__ emb,
                                const float* __restrict__ w,
                                const float* __restrict__ b,
                                float* __restrict__ x,
                                __nv_bfloat16* __restrict__ hi,
                                __nv_bfloat16* __restrict__ lo,
                                const float* __restrict__ bq,
                                const float* __restrict__ bk,
                                const float* __restrict__ bv,
                                const float* __restrict__ bg,
                                float* __restrict__ biasPacked)
{
    int row = blockIdx.x;
    int tid = threadIdx.x;                 // 256
    int tok = tokens[row];
    const float* src = emb + (size_t)tok * DD;
    float v0 = src[tid], v1 = src[tid + 256];
    size_t base = (size_t)row * DD;
    x[base + tid]       = v0;
    x[base + tid + 256] = v1;

    float s = v0 + v1, ss = v0*v0 + v1*v1;
    __shared__ float rs[8], rss[8];
    #pragma unroll
    for (int o = 16; o; o >>= 1) {
        s  += __shfl_xor_sync(0xffffffffu, s,  o);
        ss += __shfl_xor_sync(0xffffffffu, ss, o);
    }
    if ((tid & 31) == 0) { rs[tid >> 5] = s; rss[tid >> 5] = ss; }
    __syncthreads();
    float tot = 0.f, tots = 0.f;
    #pragma unroll
    for (int i = 0; i < 8; i++) { tot += rs[i]; tots += rss[i]; }
    float mean = tot * (1.f / DD);
    float var  = tots * (1.f / DD) - mean * mean;
    float rstd = rsqrtf(var + EPS);
    float o0 = (v0 - mean) * rstd * w[tid]       + b[tid];
    float o1 = (v1 - mean) * rstd * w[tid + 256] + b[tid + 256];
    __nv_bfloat16 h0 = __float2bfloat16(o0);
    __nv_bfloat16 h1 = __float2bfloat16(o1);
    hi[base + tid]       = h0;
    hi[base + tid + 256] = h1;
    lo[base + tid]       = __float2bfloat16(o0 - __bfloat162float(h0));
    lo[base + tid + 256] = __float2bfloat16(o1 - __bfloat162float(h1));

    // bias pack (first 40 blocks)
    if (row < (LL * 2048) / 512) {
        #pragma unroll
        for (int t = 0; t < 2; t++) {
            int gi = row * 512 + tid + t * 256;
            int l = gi >> 11, r = gi & 2047;
            int wsel = r >> 9, d = r & 511;
            const float* sp = (wsel == 0) ? bq : (wsel == 1) ? bk : (wsel == 2) ? bv : bg;
            biasPacked[gi] = sp[l * 512 + d];
        }
    }
    // rotary tables (first 408 blocks, lane 0..31)
    if (row < SS && tid < 32) {
        float inv = powf(10000.f, -2.f * (float)tid / 64.f);
        float ang = (float)row * inv;
        float sn, cs;
        sincosf(ang, &sn, &cs);
        g_rotcs[row * 32 + tid] = cs;
        g_rotsn[row * 32 + tid] = sn;
    }
}

// ---------------- layer norm -> bf16 hi/lo split ----------------
__global__ void layernorm_split_kernel(const float* __restrict__ x,
                                       const float* __restrict__ w,
                                       const float* __restrict__ b,
                                       __nv_bfloat16* __restrict__ hi,
                                       __nv_bfloat16* __restrict__ lo)
{
    int row = blockIdx.x;
    int tid = threadIdx.x;                 // 256
    const float* xr = x + (size_t)row * DD;
    float v0 = xr[tid], v1 = xr[tid + 256];
    float s = v0 + v1, ss = v0*v0 + v1*v1;
    __shared__ float rs[8], rss[8];
    #pragma unroll
    for (int o = 16; o; o >>= 1) {
        s  += __shfl_xor_sync(0xffffffffu, s,  o);
        ss += __shfl_xor_sync(0xffffffffu, ss, o);
    }
    if ((tid & 31) == 0) { rs[tid >> 5] = s; rss[tid >> 5] = ss; }
    __syncthreads();
    float tot = 0.f, tots = 0.f;
    #pragma unroll
    for (int i = 0; i < 8; i++) { tot += rs[i]; tots += rss[i]; }
    float mean = tot * (1.f / DD);
    float var  = tots * (1.f / DD) - mean * mean;
    float rstd = rsqrtf(var + EPS);
    float o0 = (v0 - mean) * rstd * w[tid]       + b[tid];
    float o1 = (v1 - mean) * rstd * w[tid + 256] + b[tid + 256];
    size_t base = (size_t)row * DD;
    __nv_bfloat16 h0 = __float2bfloat16(o0);
    __nv_bfloat16 h1 = __float2bfloat16(o1);
    hi[base + tid]       = h0;
    hi[base + tid + 256] = h1;
    lo[base + tid]       = __float2bfloat16(o0 - __bfloat162float(h0));
    lo[base + tid + 256] = __float2bfloat16(o1 - __bfloat162float(h1));
}

// ---------------- tensor-core GEMM (bf16 3-term, BM=192 BK=64) ----------
// warp grid 4(M) x 2(N): warp tile 48 x 64
#define APITCH 144
#define SA_H 0
#define SA_L 27648
#define SB_H 55296
#define SB_L 73728
#define GSTG 92160
#define GEMM_SMEM (2 * GSTG)

__global__ void __launch_bounds__(256, 1)
tc_gemm(const __nv_bfloat16* __restrict__ Ah,
        const __nv_bfloat16* __restrict__ Al,
        const __nv_bfloat16* __restrict__ Bh,
        const __nv_bfloat16* __restrict__ Bl,
        const float* __restrict__ bias,
        float* __restrict__ C,
        __nv_bfloat16* __restrict__ Ch,
        __nv_bfloat16* __restrict__ Cl,
        int K, int N, int epi)
{
    extern __shared__ char sm[];
    uint32_t sb = smem_u32(sm);
    int tid = threadIdx.x;
    int lane = tid & 31, wid = tid >> 5;
    int m0 = blockIdx.y * 192, n0 = blockIdx.x * 128;
    int wm = wid & 3, wn = wid >> 2;      // warp tile 48(M) x 64(N)

    int nst = K >> 6;                      // BK = 64

    float acc[24][4];
    #pragma unroll
    for (int i = 0; i < 24; i++)
        #pragma unroll
        for (int j = 0; j < 4; j++) acc[i][j] = 0.f;

    uint32_t rowoff = (uint32_t)((lane & 15) * APITCH + (lane >> 4) * 16);

    auto issue = [&](int s, int buf) {
        uint32_t dst = sb + buf * GSTG;
        int k0 = s << 6;
        #pragma unroll
        for (int it = 0; it < 6; it++) {
            int c = tid + it * 256;          // 0..1535
            int row = c >> 3, seg = c & 7;
            uint32_t doff = (uint32_t)(row * APITCH + seg * 16);
            size_t aoff = (size_t)(m0 + row) * K + k0 + seg * 8;
            cp16(dst + SA_H + doff, Ah + aoff);
            cp16(dst + SA_L + doff, Al + aoff);
        }
        #pragma unroll
        for (int it = 0; it < 4; it++) {
            int c = tid + it * 256;          // 0..1023
            int row = c >> 3, seg = c & 7;
            uint32_t doff = (uint32_t)(row * APITCH + seg * 16);
            size_t boff = (size_t)(n0 + row) * K + k0 + seg * 8;
            cp16(dst + SB_H + doff, Bh + boff);
            cp16(dst + SB_L + doff, Bl + boff);
        }
    };

    issue(0, 0);
    CP_COMMIT();

    for (int s = 0; s < nst; s++) {
        int buf = s & 1;
        if (s + 1 < nst) {
            issue(s + 1, buf ^ 1);
            CP_COMMIT();
            CP_WAIT(1);
        } else {
            CP_WAIT(0);
        }
        __syncthreads();

        uint32_t base  = sb + buf * GSTG;
        uint32_t abase = base + (uint32_t)(wm * 48 * APITCH) + rowoff;
        uint32_t bbase = base + SB_H + (uint32_t)(wn * 64 * APITCH) + rowoff;

        #pragma unroll
        for (int kst = 0; kst < 4; kst++) {
            uint32_t koff = (uint32_t)(kst * 32);
            uint32_t bh[4][4], bl[4][4];
            #pragma unroll
            for (int nb = 0; nb < 4; nb++) {
                ldsm4(bh[nb], bbase + nb * (16 * APITCH) + koff);
                ldsm4(bl[nb], bbase + (SB_L - SB_H) + nb * (16 * APITCH) + koff);
            }
            #pragma unroll
            for (int mt = 0; mt < 3; mt++) {
                uint32_t ah[4], al[4];
                ldsm4(ah, abase + SA_H + mt * (16 * APITCH) + koff);
                ldsm4(al, abase + SA_L + mt * (16 * APITCH) + koff);
                #pragma unroll
                for (int nt = 0; nt < 8; nt++)
                    mma_bf16(acc[mt * 8 + nt], ah,
                             bh[nt >> 1][nt & 1], bh[nt >> 1][(nt & 1) + 2]);
                #pragma unroll
                for (int nt = 0; nt < 8; nt++)
                    mma_bf16(acc[mt * 8 + nt], al,
                             bh[nt >> 1][nt & 1], bh[nt >> 1][(nt & 1) + 2]);
                #pragma unroll
                for (int nt = 0; nt < 8; nt++)
                    mma_bf16(acc[mt * 8 + nt], ah,
                             bl[nt >> 1][nt & 1], bl[nt >> 1][(nt & 1) + 2]);
            }
        }
        __syncthreads();
    }

    // -------- epilogue --------
    bool fused = (epi == 4);
    int which = n0 >> 9;
    float* Cb = C;
    int ldc = N, ncol0 = n0;
    if (fused) {
        Cb = C + (size_t)which * ((size_t)MROWS * 512);
        ldc = 512;
        ncol0 = n0 & 511;
    }
    bool dosilu = (epi == 1) || (epi == 3) || (fused && which == 3);

    int r_lane = lane >> 2;
    int c_lane = (lane & 3) * 2;
    #pragma unroll
    for (int mt = 0; mt < 3; mt++) {
        int r0 = m0 + wm * 48 + mt * 16 + r_lane;
        int r1 = r0 + 8;
        #pragma unroll
        for (int nt = 0; nt < 8; nt++) {
            float* a = acc[mt * 8 + nt];
            int ncb = wn * 64 + nt * 8 + c_lane;   // 0..127 in block
            float b0 = bias[n0 + ncb], b1 = bias[n0 + ncb + 1];
            float x0 = a[0] + b0, x1 = a[1] + b1;
            float y0 = a[2] + b0, y1 = a[3] + b1;
            if (dosilu) {
                x0 = x0 / (1.f + expf(-x0));
                x1 = x1 / (1.f + expf(-x1));
                y0 = y0 / (1.f + expf(-y0));
                y1 = y1 / (1.f + expf(-y1));
            }
            int nn = ncol0 + ncb;
            if (epi == 3) {
                __nv_bfloat162 h0 = __floats2bfloat162_rn(x0, x1);
                __nv_bfloat162 h1 = __floats2bfloat162_rn(y0, y1);
                float2 f0 = __bfloat1622float2(h0);
                float2 f1 = __bfloat1622float2(h1);
                __nv_bfloat162 l0 = __floats2bfloat162_rn(x0 - f0.x, x1 - f0.y);
                __nv_bfloat162 l1 = __floats2bfloat162_rn(y0 - f1.x, y1 - f1.y);
                *(__nv_bfloat162*)(Ch + (size_t)r0 * N + nn) = h0;
                *(__nv_bfloat162*)(Cl + (size_t)r0 * N + nn) = l0;
                *(__nv_bfloat162*)(Ch + (size_t)r1 * N + nn) = h1;
                *(__nv_bfloat162*)(Cl + (size_t)r1 * N + nn) = l1;
            } else {
                float* p0 = Cb + (size_t)r0 * ldc + nn;
                float* p1 = Cb + (size_t)r1 * ldc + nn;
                if (epi == 2) {
                    float2 c0 = *(float2*)p0;
                    float2 c1 = *(float2*)p1;
                    x0 += c0.x; x1 += c0.y;
                    y0 += c1.x; y1 += c1.y;
                }
                *(float2*)p0 = make_float2(x0, x1);
                *(float2*)p1 = make_float2(y0, y1);
            }
        }
    }
}

// ------ chunkwise retention (rotary fused into load): CTA per (b,h) ------
#define KT_PITCH 72
__global__ void retention_kernel(const float* __restrict__ q,
                                 const float* __restrict__ k,
                                 const float* __restrict__ v,
                                 float* __restrict__ ret)
{
    extern __shared__ float smf[];
    float* sq    = smf;                      // 68*64
    float* sk    = sq + CHK * DH;            // 68*64
    float* sv    = sk + CHK * DH;            // 68*64
    float* st    = sv + CHK * DH;            // 64*64
    float* inner = st + DH * DH;             // 68*68
    float* skT   = inner + CHK * CHK;        // 64*72
    __shared__ float gpow[CHK + 1];

    int bh = blockIdx.x;
    int b  = bh >> 3;
    int hh = bh & 7;
    int tid = threadIdx.x;
    float gamma = 1.f - exp2f(-5.f - (float)hh);
    if (tid <= CHK) gpow[tid] = powf(gamma, (float)tid);
    for (int i = tid; i < DH * DH; i += 256) st[i] = 0.f;
    __syncthreads();
    float chunk_dec = gpow[CHK];

    for (int c = 0; c < NCHUNK; c++) {
        int base = ((b * SS + c * CHK) * HH + hh) * DH;
        for (int i = tid; i < CHK * DH; i += 256) {
            int r = i >> 6, d = i & 63;
            int g = base + r * DD + d;
            int spos = c * CHK + r;
            int j = d & 31;
            float cs = g_rotcs[spos * 32 + j];
            float sn = g_rotsn[spos * 32 + j];
            float qa = q[g], ka = k[g];
            float qb, kb;
            if (d < 32) { qb = -q[g + 32]; kb = -k[g + 32]; }
            else        { qb =  q[g - 32]; kb =  k[g - 32]; }
            float qv = qa * cs + qb * sn;
            float kv = (ka * cs + kb * sn) * 0.125f;
            sq[i] = qv;
            sk[i] = kv;
            skT[d * KT_PITCH + r] = kv;
            sv[i] = v[g];
        }
        __syncthreads();

        for (int e = tid; e < CHK * 17; e += 256) {
            int i = e / 17, jg = e - i * 17;
            int j0 = jg * 4;
            float4 s = make_float4(0.f, 0.f, 0.f, 0.f);
            if (i >= j0) {
                const float* qi = sq + i * DH;
                #pragma unroll 4
                for (int d4 = 0; d4 < DH; d4 += 4) {
                    float4 qv = *(const float4*)(qi + d4);
                    float4 k0 = *(const float4*)(skT + (d4 + 0) * KT_PITCH + j0);
                    float4 k1 = *(const float4*)(skT + (d4 + 1) * KT_PITCH + j0);
                    float4 k2 = *(const float4*)(skT + (d4 + 2) * KT_PITCH + j0);
                    float4 k3 = *(const float4*)(skT + (d4 + 3) * KT_PITCH + j0);
                    s.x += qv.x*k0.x + qv.y*k1.x + qv.z*k2.x + qv.w*k3.x;
                    s.y += qv.x*k0.y + qv.y*k1.y + qv.z*k2.y + qv.w*k3.y;
                    s.z += qv.x*k0.z + qv.y*k1.z + qv.z*k2.z + qv.w*k3.z;
                    s.w += qv.x*k0.w + qv.y*k1.w + qv.z*k2.w + qv.w*k3.w;
                }
            }
            float* out = inner + i * CHK + j0;
            out[0] = (i >= j0)     ? s.x * gpow[i - j0]     : 0.f;
            out[1] = (i >= j0 + 1) ? s.y * gpow[i - j0 - 1] : 0.f;
            out[2] = (i >= j0 + 2) ? s.z * gpow[i - j0 - 2] : 0.f;
            out[3] = (i >= j0 + 3) ? s.w * gpow[i - j0 - 3] : 0.f;
        }
        __syncthreads();

        for (int e = tid; e < CHK * 16; e += 256) {
            int i = e >> 4, d4 = (e & 15) << 2;
            float4 acc = make_float4(0.f, 0.f, 0.f, 0.f);
            const float* in_i = inner + i * CHK;
            for (int j = 0; j <= i; j++) {
                float w = in_i[j];
                float4 vv = *(const float4*)(sv + j * DH + d4);
                acc.x += w * vv.x; acc.y += w * vv.y;
                acc.z += w * vv.z; acc.w += w * vv.w;
            }
            float4 a2 = make_float4(0.f, 0.f, 0.f, 0.f);
            const float* qi = sq + i * DH;
            #pragma unroll 8
            for (int ee = 0; ee < DH; ee++) {
                float qv = qi[ee];
                float4 sr = *(const float4*)(st + ee * DH + d4);
                a2.x += qv * sr.x; a2.y += qv * sr.y;
                a2.z += qv * sr.z; a2.w += qv * sr.w;
            }
            float cd = gamma * gpow[i];
            acc.x += a2.x * cd; acc.y += a2.y * cd;
            acc.z += a2.z * cd; acc.w += a2.w * cd;
            *(float4*)(&ret[base + i * DD + d4]) = acc;
        }
        __syncthreads();

        for (int e = tid; e < DH * 16; e += 256) {
            int d = e >> 4, e4 = (e & 15) << 2;
            float4 s = *(const float4*)(st + d * DH + e4);
            s.x *= chunk_dec; s.y *= chunk_dec; s.z *= chunk_dec; s.w *= chunk_dec;
            for (int j = 0; j < CHK; j++) {
                float kv = sk[j * DH + d] * gpow[CHK - 1 - j];
                float4 vv = *(const float4*)(sv + j * DH + e4);
                s.x += kv * vv.x; s.y += kv * vv.y;
                s.z += kv * vv.z; s.w += kv * vv.w;
            }
            *(float4*)(st + d * DH + e4) = s;
        }
        __syncthreads();
    }
}

// ------- per-head group norm fused with gate -> bf16 hi/lo split -------
// 256 threads = 8 groups per block
__global__ void gnorm_gate_kernel(const float* __restrict__ ret,
                                  const float* __restrict__ gnw,
                                  const float* __restrict__ gnb,
                                  const float* __restrict__ gate,
                                  __nv_bfloat16* __restrict__ ghi,
                                  __nv_bfloat16* __restrict__ glo)
{
    int grp  = blockIdx.x * 8 + (threadIdx.x >> 5);
    int hh   = grp & 7;
    int base = (grp >> 3) * DD + hh * DH;
    int lane = threadIdx.x & 31;
    float v0 = ret[base + lane], v1 = ret[base + lane + 32];
    float s = v0 + v1, ss = v0 * v0 + v1 * v1;
    #pragma unroll
    for (int o = 16; o; o >>= 1) {
        s  += __shfl_xor_sync(0xffffffffu, s,  o);
        ss += __shfl_xor_sync(0xffffffffu, ss, o);
    }
    float mean = s * (1.f / DH);
    float var  = ss * (1.f / DH) - mean * mean;
    float rstd = rsqrtf(var + EPS);
    int wi = hh * DH + lane;
    float o0 = (v0 - mean) * rstd * gnw[wi]      + gnb[wi];
    float o1 = (v1 - mean) * rstd * gnw[wi + 32] + gnb[wi + 32];
    float p0 = gate[base + lane]      * o0;
    float p1 = gate[base + lane + 32] * o1;
    __nv_bfloat16 h0 = __float2bfloat16(p0);
    __nv_bfloat16 h1 = __float2bfloat16(p1);
    ghi[base + lane]      = h0;
    ghi[base + lane + 32] = h1;
    glo[base + lane]      = __float2bfloat16(p0 - __bfloat162float(h0));
    glo[base + lane + 32] = __float2bfloat16(p1 - __bfloat162float(h1));
}

// ---------------- host orchestration ----------------
extern "C" void kernel_launch(void* const* d_in, const int* in_sizes, int n_in,
                              void* d_out, int out_size)
{
    const int*   tokens = (const int*)  d_in[0];
    const float* emb    = (const float*)d_in[1];
    const float* Wq = (const float*)d_in[2],  * bq = (const float*)d_in[3];
    const float* Wk = (const float*)d_in[4],  * bk = (const float*)d_in[5];
    const float* Wv = (const float*)d_in[6],  * bv = (const float*)d_in[7];
    const float* Wg = (const float*)d_in[8],  * bg = (const float*)d_in[9];
    const float* Wo = (const float*)d_in[10], * bo = (const float*)d_in[11];
    const float* gnw  = (const float*)d_in[12], * gnb  = (const float*)d_in[13];
    const float* ln1w = (const float*)d_in[14], * ln1b = (const float*)d_in[15];
    const float* ln2w = (const float*)d_in[16], * ln2b = (const float*)d_in[17];
    const float* w1 = (const float*)d_in[18], * b1 = (const float*)d_in[19];
    const float* w2 = (const float*)d_in[20], * b2 = (const float*)d_in[21];

    float* x = (float*)d_out;

    float* fb = nullptr;
    cudaGetSymbolAddress((void**)&fb, g_scratch);
    const size_t SZ = (size_t)MROWS * DD;
    float* q    = fb;                        // q,k,v,gate consecutive (epi4!)
    float* ret  = fb + 4 * SZ;

    __nv_bfloat16* ab = nullptr;
    cudaGetSymbolAddress((void**)&ab, g_act);
    __nv_bfloat16* h_hi  = ab;
    __nv_bfloat16* h_lo  = ab + SZ;
    __nv_bfloat16* g_hi  = ab + 2 * SZ;
    __nv_bfloat16* g_lo  = ab + 3 * SZ;
    __nv_bfloat16* ff_hi = ab + 4 * SZ;
    __nv_bfloat16* ff_lo = ab + 8 * SZ;

    __nv_bfloat16* wts = nullptr;
    cudaGetSymbolAddress((void**)&wts, g_wts);
    __nv_bfloat16* qkvg_h = wts;             // [L][2048][512]
    __nv_bfloat16* qkvg_l = wts + 4 * W5;
    __nv_bfloat16* wo_h   = wts + 8 * W5;
    __nv_bfloat16* wo_l   = wts + 9 * W5;
    __nv_bfloat16* w1_h   = wts + 10 * W5;
    __nv_bfloat16* w1_l   = wts + 10 * W5 + WF;
    __nv_bfloat16* w2_h   = wts + 10 * W5 + 2 * WF;
    __nv_bfloat16* w2_l   = wts + 10 * W5 + 3 * WF;

    float* biasP = nullptr;
    cudaGetSymbolAddress((void**)&biasP, g_bias);

    const int RET_SMEM = (3 * CHK * DH + DH * DH + CHK * CHK + DH * KT_PITCH)
                         * (int)sizeof(float);
    cudaFuncSetAttribute(retention_kernel,
                         cudaFuncAttributeMaxDynamicSharedMemorySize, RET_SMEM);
    cudaFuncSetAttribute(tc_gemm,
                         cudaFuncAttributeMaxDynamicSharedMemorySize, GEMM_SMEM);

    dim3 wb(32, 8);
    dim3 gemmQKVG(2048 / 128, MROWS / 192);  // (16, 34)
    dim3 gemmO(DD / 128, MROWS / 192);       // (4, 34)
    dim3 gemmF1(FFN / 128, MROWS / 192);     // (16, 34)
    dim3 gemmF2(DD / 128, MROWS / 192);      // (4, 34)

    for (int l = 0; l < LL; l++) {
        const size_t oQW = (size_t)l * 2048 * DD;
        const size_t oW  = (size_t)l * DD * DD;
        const size_t oF  = (size_t)l * DD * FFN;
        const size_t ob  = (size_t)l * DD;
        const size_t obf = (size_t)l * FFN;

        if (l == 0) {
            // launch 0: square weight conversion
            wconv5_kernel<<<dim3(16, 16, 5 * LL), wb>>>(Wq, Wk, Wv, Wg, Wo,
                                                        qkvg_h, qkvg_l, wo_h, wo_l);
            // launch 1: embed + ln1(l0) + bias pack + rot tables
            embed_ln_kernel<<<MROWS, 256>>>(tokens, emb, ln1w, ln1b, x, h_hi, h_lo,
                                            bq, bk, bv, bg, biasP);
        } else {
            layernorm_split_kernel<<<MROWS, 256>>>(x, ln1w + ob, ln1b + ob, h_hi, h_lo);
        }

        // launch 2 (l=0): fused qkvg GEMM
        tc_gemm<<<gemmQKVG, 256, GEMM_SMEM>>>(h_hi, h_lo, qkvg_h + oQW, qkvg_l + oQW,
                                              biasP + (size_t)l * 2048, q,
                                              nullptr, nullptr, DD, 2048, 4);

        // launch 3: retention (rotary fused)
        retention_kernel<<<BB * HH, 256, RET_SMEM>>>(q, q + SZ, q + 2 * SZ, ret);

        // launch 4: gnorm+gate
        gnorm_gate_kernel<<<MROWS, 256>>>(ret, gnw + ob, gnb + ob, q + 3 * SZ,
                                          g_hi, g_lo);

        // launch 5 (l=0): Wo GEMM
        tc_gemm<<<gemmO, 256, GEMM_SMEM>>>(g_hi, g_lo, wo_h + oW, wo_l + oW,
                                           bo + ob, x, nullptr, nullptr, DD, DD, 2);

        if (l == 0) {
            // ff weight conversion (needed from here on)
            wconv_kernel<<<dim3(FFN / 32, DD / 32, LL), wb>>>(w1, w1_h, w1_l, DD, FFN);
            wconv_kernel<<<dim3(DD / 32, FFN / 32, LL), wb>>>(w2, w2_h, w2_l, FFN, DD);
        }

        layernorm_split_kernel<<<MROWS, 256>>>(x, ln2w + ob, ln2b + ob, h_hi, h_lo);

        tc_gemm<<<gemmF1, 256, GEMM_SMEM>>>(h_hi, h_lo, w1_h + oF, w1_l + oF,
                                            b1 + obf, nullptr, ff_hi, ff_lo,
                                            DD, FFN, 3);
        tc_gemm<<<gemmF2, 256, GEMM_SMEM>>>(ff_hi, ff_lo, w2_h + oF, w2_l + oF,
                                            b2 + ob, x, nullptr, nullptr,
                                            FFN, DD, 2);
    }
}

// round 6
// speedup vs baseline: 2.4982x; 1.0006x over previous
#include <cuda_runtime.h>
#include <cuda_bf16.h>
#include <math.h>
#include <stdint.h>

// ---------------- problem constants ----------------
#define BB   16
#define SS   408
#define DD   512
#define LL   10
#define FFN  2048
#define HH   8
#define DH   64
#define CHK  68
#define NCHUNK (SS/CHK)     // 6
#define MROWS (BB*SS)       // 6528
#define EPS  1e-5f

// ---------------- scratch (no allocations allowed) ----------------
// fp32: q, k, v, gate (consecutive!), ret
__device__ __align__(16) float g_scratch[(size_t)5 * MROWS * DD];
// per-chunk KV summaries: [b*H][chunk][64][64]
__device__ __align__(16) float g_chunkS[(size_t)BB * HH * NCHUNK * DH * DH];
// bf16 activations hi/lo: h(2) + g(2) + ff(8) in units of MROWS*DD
__device__ __align__(16) __nv_bfloat16 g_act[(size_t)12 * MROWS * DD];
// bf16 hi/lo pre-transposed weights
#define W5  ((size_t)LL * DD * DD)
#define WF  ((size_t)LL * DD * FFN)
__device__ __align__(16) __nv_bfloat16 g_wts[10 * W5 + 4 * WF];
// packed qkvg bias [L][2048]
__device__ __align__(16) float g_bias[(size_t)LL * 2048];
// rotary tables [S][32]
__device__ __align__(16) float g_rotcs[SS * 32];
__device__ __align__(16) float g_rotsn[SS * 32];

// ================= PTX helpers (family-portable: sm_80+) =================
__device__ __forceinline__ uint32_t smem_u32(const void* p) {
    uint32_t a;
    asm("{ .reg .u64 t; cvta.to.shared.u64 t, %1; cvt.u32.u64 %0, t; }"
        : "=r"(a) : "l"(p));
    return a;
}
__device__ __forceinline__ void cp16(uint32_t dst, const void* src) {
    asm volatile("cp.async.cg.shared.global [%0], [%1], 16;"
                 :: "r"(dst), "l"(src));
}
#define CP_COMMIT() asm volatile("cp.async.commit_group;" ::: "memory")
#define CP_WAIT(n)  asm volatile("cp.async.wait_group %0;" :: "n"(n) : "memory")

__device__ __forceinline__ void ldsm4(uint32_t* r, uint32_t addr) {
    asm volatile("ldmatrix.sync.aligned.m8n8.x4.shared.b16 {%0,%1,%2,%3}, [%4];"
                 : "=r"(r[0]), "=r"(r[1]), "=r"(r[2]), "=r"(r[3]) : "r"(addr));
}
__device__ __forceinline__ void mma_bf16(float* c, const uint32_t* a,
                                         uint32_t b0, uint32_t b1) {
    asm volatile(
        "mma.sync.aligned.m16n8k16.row.col.f32.bf16.bf16.f32 "
        "{%0,%1,%2,%3}, {%4,%5,%6,%7}, {%8,%9}, {%0,%1,%2,%3};"
        : "+f"(c[0]), "+f"(c[1]), "+f"(c[2]), "+f"(c[3])
        : "r"(a[0]), "r"(a[1]), "r"(a[2]), "r"(a[3]), "r"(b0), "r"(b1));
}

// ------- weight transpose + bf16 hi/lo split: 5 square mats fused -------
__global__ void wconv5_kernel(const float* __restrict__ Wq, const float* __restrict__ Wk,
                              const float* __restrict__ Wv, const float* __restrict__ Wg,
                              const float* __restrict__ Wo,
                              __nv_bfloat16* __restrict__ qkvg_h, __nv_bfloat16* __restrict__ qkvg_l,
                              __nv_bfloat16* __restrict__ wo_h,   __nv_bfloat16* __restrict__ wo_l)
{
    __shared__ float t[32][33];
    int z = blockIdx.z;
    int m = z / LL, l = z - m * LL;
    const float* S = (m == 0) ? Wq : (m == 1) ? Wk : (m == 2) ? Wv : (m == 3) ? Wg : Wo;
    const float* s = S + (size_t)l * DD * DD;
    int n0 = blockIdx.x * 32, k0 = blockIdx.y * 32;
    int tx = threadIdx.x, ty = threadIdx.y;
    #pragma unroll
    for (int r = ty; r < 32; r += 8)
        t[r][tx] = s[(size_t)(k0 + r) * DD + n0 + tx];
    __syncthreads();
    __nv_bfloat16* hi;
    __nv_bfloat16* lo;
    size_t dbase;
    if (m < 4) {
        hi = qkvg_h; lo = qkvg_l;
        dbase = (size_t)l * 2048 * DD + (size_t)m * 512 * DD;
    } else {
        hi = wo_h; lo = wo_l;
        dbase = (size_t)l * DD * DD;
    }
    #pragma unroll
    for (int r = ty; r < 32; r += 8) {
        float x = t[tx][r];
        __nv_bfloat16 h = __float2bfloat16(x);
        float rem = x - __bfloat162float(h);
        size_t o = dbase + (size_t)(n0 + r) * DD + k0 + tx;
        hi[o] = h;
        lo[o] = __float2bfloat16(rem);
    }
}

// ---------------- generic weight transpose (ff mats) --------------
__global__ void wconv_kernel(const float* __restrict__ src,
                             __nv_bfloat16* __restrict__ hi,
                             __nv_bfloat16* __restrict__ lo,
                             int K, int N)
{
    __shared__ float t[32][33];
    int n0 = blockIdx.x * 32, k0 = blockIdx.y * 32;
    const float* s = src + (size_t)blockIdx.z * K * N;
    int tx = threadIdx.x, ty = threadIdx.y;
    #pragma unroll
    for (int r = ty; r < 32; r += 8)
        t[r][tx] = s[(size_t)(k0 + r) * N + n0 + tx];
    __syncthreads();
    size_t dbase = (size_t)blockIdx.z * N * K;
    #pragma unroll
    for (int r = ty; r < 32; r += 8) {
        float x = t[tx][r];
        __nv_bfloat16 h = __float2bfloat16(x);
        float rem = x - __bfloat162float(h);
        size_t o = dbase + (size_t)(n0 + r) * K + k0 + tx;
        hi[o] = h;
        lo[o] = __float2bfloat16(rem);
    }
}

// ---- fused: embedding gather + LN(layer0) split + bias pack + rot tables ----
__global__ void embed_ln_kernel(const int* __restrict__ tokens,
                                const float* __restrict__ emb,
                                const float* __restrict__ w,
                                const float* __restrict__ b,
                                float* __restrict__ x,
                                __nv_bfloat16* __restrict__ hi,
                                __nv_bfloat16* __restrict__ lo,
                                const float* __restrict__ bq,
                                const float* __restrict__ bk,
                                const float* __restrict__ bv,
                                const float* __restrict__ bg,
                                float* __restrict__ biasPacked)
{
    int row = blockIdx.x;
    int tid = threadIdx.x;                 // 256
    int tok = tokens[row];
    const float* src = emb + (size_t)tok * DD;
    float v0 = src[tid], v1 = src[tid + 256];
    size_t base = (size_t)row * DD;
    x[base + tid]       = v0;
    x[base + tid + 256] = v1;

    float s = v0 + v1, ss = v0*v0 + v1*v1;
    __shared__ float rs[8], rss[8];
    #pragma unroll
    for (int o = 16; o; o >>= 1) {
        s  += __shfl_xor_sync(0xffffffffu, s,  o);
        ss += __shfl_xor_sync(0xffffffffu, ss, o);
    }
    if ((tid & 31) == 0) { rs[tid >> 5] = s; rss[tid >> 5] = ss; }
    __syncthreads();
    float tot = 0.f, tots = 0.f;
    #pragma unroll
    for (int i = 0; i < 8; i++) { tot += rs[i]; tots += rss[i]; }
    float mean = tot * (1.f / DD);
    float var  = tots * (1.f / DD) - mean * mean;
    float rstd = rsqrtf(var + EPS);
    float o0 = (v0 - mean) * rstd * w[tid]       + b[tid];
    float o1 = (v1 - mean) * rstd * w[tid + 256] + b[tid + 256];
    __nv_bfloat16 h0 = __float2bfloat16(o0);
    __nv_bfloat16 h1 = __float2bfloat16(o1);
    hi[base + tid]       = h0;
    hi[base + tid + 256] = h1;
    lo[base + tid]       = __float2bfloat16(o0 - __bfloat162float(h0));
    lo[base + tid + 256] = __float2bfloat16(o1 - __bfloat162float(h1));

    if (row < (LL * 2048) / 512) {
        #pragma unroll
        for (int t = 0; t < 2; t++) {
            int gi = row * 512 + tid + t * 256;
            int l = gi >> 11, r = gi & 2047;
            int wsel = r >> 9, d = r & 511;
            const float* sp = (wsel == 0) ? bq : (wsel == 1) ? bk : (wsel == 2) ? bv : bg;
            biasPacked[gi] = sp[l * 512 + d];
        }
    }
    if (row < SS && tid < 32) {
        float inv = powf(10000.f, -2.f * (float)tid / 64.f);
        float ang = (float)row * inv;
        float sn, cs;
        sincosf(ang, &sn, &cs);
        g_rotcs[row * 32 + tid] = cs;
        g_rotsn[row * 32 + tid] = sn;
    }
}

// ---------------- layer norm -> bf16 hi/lo split ----------------
__global__ void layernorm_split_kernel(const float* __restrict__ x,
                                       const float* __restrict__ w,
                                       const float* __restrict__ b,
                                       __nv_bfloat16* __restrict__ hi,
                                       __nv_bfloat16* __restrict__ lo)
{
    int row = blockIdx.x;
    int tid = threadIdx.x;                 // 256
    const float* xr = x + (size_t)row * DD;
    float v0 = xr[tid], v1 = xr[tid + 256];
    float s = v0 + v1, ss = v0*v0 + v1*v1;
    __shared__ float rs[8], rss[8];
    #pragma unroll
    for (int o = 16; o; o >>= 1) {
        s  += __shfl_xor_sync(0xffffffffu, s,  o);
        ss += __shfl_xor_sync(0xffffffffu, ss, o);
    }
    if ((tid & 31) == 0) { rs[tid >> 5] = s; rss[tid >> 5] = ss; }
    __syncthreads();
    float tot = 0.f, tots = 0.f;
    #pragma unroll
    for (int i = 0; i < 8; i++) { tot += rs[i]; tots += rss[i]; }
    float mean = tot * (1.f / DD);
    float var  = tots * (1.f / DD) - mean * mean;
    float rstd = rsqrtf(var + EPS);
    float o0 = (v0 - mean) * rstd * w[tid]       + b[tid];
    float o1 = (v1 - mean) * rstd * w[tid + 256] + b[tid + 256];
    size_t base = (size_t)row * DD;
    __nv_bfloat16 h0 = __float2bfloat16(o0);
    __nv_bfloat16 h1 = __float2bfloat16(o1);
    hi[base + tid]       = h0;
    hi[base + tid + 256] = h1;
    lo[base + tid]       = __float2bfloat16(o0 - __bfloat162float(h0));
    lo[base + tid + 256] = __float2bfloat16(o1 - __bfloat162float(h1));
}

// ---------------- tensor-core GEMM (bf16 3-term, BM=192 BK=64) ----------
#define APITCH 144
#define SA_H 0
#define SA_L 27648
#define SB_H 55296
#define SB_L 73728
#define GSTG 92160
#define GEMM_SMEM (2 * GSTG)

__global__ void __launch_bounds__(256, 1)
tc_gemm(const __nv_bfloat16* __restrict__ Ah,
        const __nv_bfloat16* __restrict__ Al,
        const __nv_bfloat16* __restrict__ Bh,
        const __nv_bfloat16* __restrict__ Bl,
        const float* __restrict__ bias,
        float* __restrict__ C,
        __nv_bfloat16* __restrict__ Ch,
        __nv_bfloat16* __restrict__ Cl,
        int K, int N, int epi)
{
    extern __shared__ char sm[];
    uint32_t sb = smem_u32(sm);
    int tid = threadIdx.x;
    int lane = tid & 31, wid = tid >> 5;
    int m0 = blockIdx.y * 192, n0 = blockIdx.x * 128;
    int wm = wid & 3, wn = wid >> 2;      // warp tile 48(M) x 64(N)

    int nst = K >> 6;                      // BK = 64

    float acc[24][4];
    #pragma unroll
    for (int i = 0; i < 24; i++)
        #pragma unroll
        for (int j = 0; j < 4; j++) acc[i][j] = 0.f;

    uint32_t rowoff = (uint32_t)((lane & 15) * APITCH + (lane >> 4) * 16);

    auto issue = [&](int s, int buf) {
        uint32_t dst = sb + buf * GSTG;
        int k0 = s << 6;
        #pragma unroll
        for (int it = 0; it < 6; it++) {
            int c = tid + it * 256;
            int row = c >> 3, seg = c & 7;
            uint32_t doff = (uint32_t)(row * APITCH + seg * 16);
            size_t aoff = (size_t)(m0 + row) * K + k0 + seg * 8;
            cp16(dst + SA_H + doff, Ah + aoff);
            cp16(dst + SA_L + doff, Al + aoff);
        }
        #pragma unroll
        for (int it = 0; it < 4; it++) {
            int c = tid + it * 256;
            int row = c >> 3, seg = c & 7;
            uint32_t doff = (uint32_t)(row * APITCH + seg * 16);
            size_t boff = (size_t)(n0 + row) * K + k0 + seg * 8;
            cp16(dst + SB_H + doff, Bh + boff);
            cp16(dst + SB_L + doff, Bl + boff);
        }
    };

    issue(0, 0);
    CP_COMMIT();

    for (int s = 0; s < nst; s++) {
        int buf = s & 1;
        if (s + 1 < nst) {
            issue(s + 1, buf ^ 1);
            CP_COMMIT();
            CP_WAIT(1);
        } else {
            CP_WAIT(0);
        }
        __syncthreads();

        uint32_t base  = sb + buf * GSTG;
        uint32_t abase = base + (uint32_t)(wm * 48 * APITCH) + rowoff;
        uint32_t bbase = base + SB_H + (uint32_t)(wn * 64 * APITCH) + rowoff;

        #pragma unroll
        for (int kst = 0; kst < 4; kst++) {
            uint32_t koff = (uint32_t)(kst * 32);
            uint32_t bh[4][4], bl[4][4];
            #pragma unroll
            for (int nb = 0; nb < 4; nb++) {
                ldsm4(bh[nb], bbase + nb * (16 * APITCH) + koff);
                ldsm4(bl[nb], bbase + (SB_L - SB_H) + nb * (16 * APITCH) + koff);
            }
            #pragma unroll
            for (int mt = 0; mt < 3; mt++) {
                uint32_t ah[4], al[4];
                ldsm4(ah, abase + SA_H + mt * (16 * APITCH) + koff);
                ldsm4(al, abase + SA_L + mt * (16 * APITCH) + koff);
                #pragma unroll
                for (int nt = 0; nt < 8; nt++)
                    mma_bf16(acc[mt * 8 + nt], ah,
                             bh[nt >> 1][nt & 1], bh[nt >> 1][(nt & 1) + 2]);
                #pragma unroll
                for (int nt = 0; nt < 8; nt++)
                    mma_bf16(acc[mt * 8 + nt], al,
                             bh[nt >> 1][nt & 1], bh[nt >> 1][(nt & 1) + 2]);
                #pragma unroll
                for (int nt = 0; nt < 8; nt++)
                    mma_bf16(acc[mt * 8 + nt], ah,
                             bl[nt >> 1][nt & 1], bl[nt >> 1][(nt & 1) + 2]);
            }
        }
        __syncthreads();
    }

    // -------- epilogue --------
    bool fused = (epi == 4);
    int which = n0 >> 9;
    float* Cb = C;
    int ldc = N, ncol0 = n0;
    if (fused) {
        Cb = C + (size_t)which * ((size_t)MROWS * 512);
        ldc = 512;
        ncol0 = n0 & 511;
    }
    bool dosilu = (epi == 1) || (epi == 3) || (fused && which == 3);

    int r_lane = lane >> 2;
    int c_lane = (lane & 3) * 2;
    #pragma unroll
    for (int mt = 0; mt < 3; mt++) {
        int r0 = m0 + wm * 48 + mt * 16 + r_lane;
        int r1 = r0 + 8;
        #pragma unroll
        for (int nt = 0; nt < 8; nt++) {
            float* a = acc[mt * 8 + nt];
            int ncb = wn * 64 + nt * 8 + c_lane;
            float b0 = bias[n0 + ncb], b1 = bias[n0 + ncb + 1];
            float x0 = a[0] + b0, x1 = a[1] + b1;
            float y0 = a[2] + b0, y1 = a[3] + b1;
            if (dosilu) {
                x0 = x0 / (1.f + expf(-x0));
                x1 = x1 / (1.f + expf(-x1));
                y0 = y0 / (1.f + expf(-y0));
                y1 = y1 / (1.f + expf(-y1));
            }
            int nn = ncol0 + ncb;
            if (epi == 3) {
                __nv_bfloat162 h0 = __floats2bfloat162_rn(x0, x1);
                __nv_bfloat162 h1 = __floats2bfloat162_rn(y0, y1);
                float2 f0 = __bfloat1622float2(h0);
                float2 f1 = __bfloat1622float2(h1);
                __nv_bfloat162 l0 = __floats2bfloat162_rn(x0 - f0.x, x1 - f0.y);
                __nv_bfloat162 l1 = __floats2bfloat162_rn(y0 - f1.x, y1 - f1.y);
                *(__nv_bfloat162*)(Ch + (size_t)r0 * N + nn) = h0;
                *(__nv_bfloat162*)(Cl + (size_t)r0 * N + nn) = l0;
                *(__nv_bfloat162*)(Ch + (size_t)r1 * N + nn) = h1;
                *(__nv_bfloat162*)(Cl + (size_t)r1 * N + nn) = l1;
            } else {
                float* p0 = Cb + (size_t)r0 * ldc + nn;
                float* p1 = Cb + (size_t)r1 * ldc + nn;
                if (epi == 2) {
                    float2 c0 = *(float2*)p0;
                    float2 c1 = *(float2*)p1;
                    x0 += c0.x; x1 += c0.y;
                    y0 += c1.x; y1 += c1.y;
                }
                *(float2*)p0 = make_float2(x0, x1);
                *(float2*)p1 = make_float2(y0, y1);
            }
        }
    }
}

// ======== retention phase 1: per-chunk KV summary (chunk-parallel) ========
// S_c[d][e] = sum_j k'[j][d] * gamma^(C-1-j) * v[j][e]   (k' = rotary, scaled)
__global__ void __launch_bounds__(256)
ret_phase1(const float* __restrict__ k, const float* __restrict__ v,
           float* __restrict__ chunkS)
{
    __shared__ float sk[CHK * DH];
    __shared__ float sv[CHK * DH];
    __shared__ float gpow[CHK + 1];

    int z  = blockIdx.x;                  // bh * NCHUNK + c
    int bh = z / NCHUNK, c = z - bh * NCHUNK;
    int b  = bh >> 3, hh = bh & 7;
    int tid = threadIdx.x;
    float gamma = 1.f - exp2f(-5.f - (float)hh);
    if (tid <= CHK) gpow[tid] = powf(gamma, (float)tid);
    __syncthreads();

    int base = ((b * SS + c * CHK) * HH + hh) * DH;
    for (int i = tid; i < CHK * DH; i += 256) {
        int r = i >> 6, d = i & 63;
        int g = base + r * DD + d;
        int spos = c * CHK + r;
        int j = d & 31;
        float cs = g_rotcs[spos * 32 + j];
        float sn = g_rotsn[spos * 32 + j];
        float ka = k[g];
        float kb = (d < 32) ? -k[g + 32] : k[g - 32];
        sk[i] = (ka * cs + kb * sn) * 0.125f * gpow[CHK - 1 - r];
        sv[i] = v[g];
    }
    __syncthreads();

    float* out = chunkS + (size_t)z * (DH * DH);
    for (int e = tid; e < DH * 16; e += 256) {
        int d = e >> 4, e4 = (e & 15) << 2;
        float4 s = make_float4(0.f, 0.f, 0.f, 0.f);
        for (int j = 0; j < CHK; j++) {
            float kv = sk[j * DH + d];
            float4 vv = *(const float4*)(sv + j * DH + e4);
            s.x += kv * vv.x; s.y += kv * vv.y;
            s.z += kv * vv.z; s.w += kv * vv.w;
        }
        *(float4*)(out + d * DH + e4) = s;
    }
}

// ======== retention phase 2: per-chunk output (chunk-parallel) ========
#define KT_PITCH 72
#define RET2_FLOATS (2 * CHK * DH + DH * KT_PITCH + DH * DH + CHK * CHK)
__global__ void __launch_bounds__(256)
ret_phase2(const float* __restrict__ q, const float* __restrict__ k,
           const float* __restrict__ v, const float* __restrict__ chunkS,
           float* __restrict__ ret)
{
    extern __shared__ float smf[];
    float* sq    = smf;                      // 68*64
    float* sv    = sq + CHK * DH;            // 68*64
    float* skT   = sv + CHK * DH;            // 64*72
    float* st    = skT + DH * KT_PITCH;      // 64*64 incoming state
    float* inner = st + DH * DH;             // 68*68
    __shared__ float gpow[CHK + 1];

    int z  = blockIdx.x;
    int bh = z / NCHUNK, c = z - bh * NCHUNK;
    int b  = bh >> 3, hh = bh & 7;
    int tid = threadIdx.x;
    float gamma = 1.f - exp2f(-5.f - (float)hh);
    if (tid <= CHK) gpow[tid] = powf(gamma, (float)tid);
    __syncthreads();
    float chunk_dec = gpow[CHK];

    int base = ((b * SS + c * CHK) * HH + hh) * DH;
    for (int i = tid; i < CHK * DH; i += 256) {
        int r = i >> 6, d = i & 63;
        int g = base + r * DD + d;
        int spos = c * CHK + r;
        int j = d & 31;
        float cs = g_rotcs[spos * 32 + j];
        float sn = g_rotsn[spos * 32 + j];
        float qa = q[g], ka = k[g];
        float qb, kb;
        if (d < 32) { qb = -q[g + 32]; kb = -k[g + 32]; }
        else        { qb =  q[g - 32]; kb =  k[g - 32]; }
        sq[i] = qa * cs + qb * sn;
        skT[d * KT_PITCH + r] = (ka * cs + kb * sn) * 0.125f;
        sv[i] = v[g];
    }
    // assemble incoming state: st = sum_{c'<c} chunk_dec^(c-1-c') * S_{c'}
    {
        const float* Sbase = chunkS + (size_t)(bh * NCHUNK) * (DH * DH);
        #pragma unroll
        for (int g4 = 0; g4 < 4; g4++) {
            int idx = tid * 16 + g4 * 4;          // 0..4095
            float4 acc = make_float4(0.f, 0.f, 0.f, 0.f);
            float w = 1.f;
            for (int cc = c - 1; cc >= 0; cc--) {
                float4 sv4 = *(const float4*)(Sbase + (size_t)cc * (DH * DH) + idx);
                acc.x += w * sv4.x; acc.y += w * sv4.y;
                acc.z += w * sv4.z; acc.w += w * sv4.w;
                w *= chunk_dec;
            }
            *(float4*)(st + idx) = acc;
        }
    }
    __syncthreads();

    // inner[i][j] = (q_i . k_j) * gamma^(i-j)
    for (int e = tid; e < CHK * 17; e += 256) {
        int i = e / 17, jg = e - i * 17;
        int j0 = jg * 4;
        float4 s = make_float4(0.f, 0.f, 0.f, 0.f);
        if (i >= j0) {
            const float* qi = sq + i * DH;
            #pragma unroll 4
            for (int d4 = 0; d4 < DH; d4 += 4) {
                float4 qv = *(const float4*)(qi + d4);
                float4 k0 = *(const float4*)(skT + (d4 + 0) * KT_PITCH + j0);
                float4 k1 = *(const float4*)(skT + (d4 + 1) * KT_PITCH + j0);
                float4 k2 = *(const float4*)(skT + (d4 + 2) * KT_PITCH + j0);
                float4 k3 = *(const float4*)(skT + (d4 + 3) * KT_PITCH + j0);
                s.x += qv.x*k0.x + qv.y*k1.x + qv.z*k2.x + qv.w*k3.x;
                s.y += qv.x*k0.y + qv.y*k1.y + qv.z*k2.y + qv.w*k3.y;
                s.z += qv.x*k0.z + qv.y*k1.z + qv.z*k2.z + qv.w*k3.z;
                s.w += qv.x*k0.w + qv.y*k1.w + qv.z*k2.w + qv.w*k3.w;
            }
        }
        float* out = inner + i * CHK + j0;
        out[0] = (i >= j0)     ? s.x * gpow[i - j0]     : 0.f;
        out[1] = (i >= j0 + 1) ? s.y * gpow[i - j0 - 1] : 0.f;
        out[2] = (i >= j0 + 2) ? s.z * gpow[i - j0 - 2] : 0.f;
        out[3] = (i >= j0 + 3) ? s.w * gpow[i - j0 - 3] : 0.f;
    }
    __syncthreads();

    // out[i][d] = sum_{j<=i} inner[i][j] v[j][d] + (q_i . st[:,d]) gamma^(i+1)
    for (int e = tid; e < CHK * 16; e += 256) {
        int i = e >> 4, d4 = (e & 15) << 2;
        float4 acc = make_float4(0.f, 0.f, 0.f, 0.f);
        const float* in_i = inner + i * CHK;
        for (int j = 0; j <= i; j++) {
            float w = in_i[j];
            float4 vv = *(const float4*)(sv + j * DH + d4);
            acc.x += w * vv.x; acc.y += w * vv.y;
            acc.z += w * vv.z; acc.w += w * vv.w;
        }
        float4 a2 = make_float4(0.f, 0.f, 0.f, 0.f);
        const float* qi = sq + i * DH;
        #pragma unroll 8
        for (int ee = 0; ee < DH; ee++) {
            float qv = qi[ee];
            float4 sr = *(const float4*)(st + ee * DH + d4);
            a2.x += qv * sr.x; a2.y += qv * sr.y;
            a2.z += qv * sr.z; a2.w += qv * sr.w;
        }
        float cd = gamma * gpow[i];
        acc.x += a2.x * cd; acc.y += a2.y * cd;
        acc.z += a2.z * cd; acc.w += a2.w * cd;
        *(float4*)(&ret[base + i * DD + d4]) = acc;
    }
}

// ------- per-head group norm fused with gate -> bf16 hi/lo split -------
__global__ void gnorm_gate_kernel(const float* __restrict__ ret,
                                  const float* __restrict__ gnw,
                                  const float* __restrict__ gnb,
                                  const float* __restrict__ gate,
                                  __nv_bfloat16* __restrict__ ghi,
                                  __nv_bfloat16* __restrict__ glo)
{
    int grp  = blockIdx.x * 8 + (threadIdx.x >> 5);
    int hh   = grp & 7;
    int base = (grp >> 3) * DD + hh * DH;
    int lane = threadIdx.x & 31;
    float v0 = ret[base + lane], v1 = ret[base + lane + 32];
    float s = v0 + v1, ss = v0 * v0 + v1 * v1;
    #pragma unroll
    for (int o = 16; o; o >>= 1) {
        s  += __shfl_xor_sync(0xffffffffu, s,  o);
        ss += __shfl_xor_sync(0xffffffffu, ss, o);
    }
    float mean = s * (1.f / DH);
    float var  = ss * (1.f / DH) - mean * mean;
    float rstd = rsqrtf(var + EPS);
    int wi = hh * DH + lane;
    float o0 = (v0 - mean) * rstd * gnw[wi]      + gnb[wi];
    float o1 = (v1 - mean) * rstd * gnw[wi + 32] + gnb[wi + 32];
    float p0 = gate[base + lane]      * o0;
    float p1 = gate[base + lane + 32] * o1;
    __nv_bfloat16 h0 = __float2bfloat16(p0);
    __nv_bfloat16 h1 = __float2bfloat16(p1);
    ghi[base + lane]      = h0;
    ghi[base + lane + 32] = h1;
    glo[base + lane]      = __float2bfloat16(p0 - __bfloat162float(h0));
    glo[base + lane + 32] = __float2bfloat16(p1 - __bfloat162float(h1));
}

// ---------------- host orchestration ----------------
extern "C" void kernel_launch(void* const* d_in, const int* in_sizes, int n_in,
                              void* d_out, int out_size)
{
    const int*   tokens = (const int*)  d_in[0];
    const float* emb    = (const float*)d_in[1];
    const float* Wq = (const float*)d_in[2],  * bq = (const float*)d_in[3];
    const float* Wk = (const float*)d_in[4],  * bk = (const float*)d_in[5];
    const float* Wv = (const float*)d_in[6],  * bv = (const float*)d_in[7];
    const float* Wg = (const float*)d_in[8],  * bg = (const float*)d_in[9];
    const float* Wo = (const float*)d_in[10], * bo = (const float*)d_in[11];
    const float* gnw  = (const float*)d_in[12], * gnb  = (const float*)d_in[13];
    const float* ln1w = (const float*)d_in[14], * ln1b = (const float*)d_in[15];
    const float* ln2w = (const float*)d_in[16], * ln2b = (const float*)d_in[17];
    const float* w1 = (const float*)d_in[18], * b1 = (const float*)d_in[19];
    const float* w2 = (const float*)d_in[20], * b2 = (const float*)d_in[21];

    float* x = (float*)d_out;

    float* fb = nullptr;
    cudaGetSymbolAddress((void**)&fb, g_scratch);
    const size_t SZ = (size_t)MROWS * DD;
    float* q    = fb;                        // q,k,v,gate consecutive (epi4!)
    float* ret  = fb + 4 * SZ;

    float* chunkS = nullptr;
    cudaGetSymbolAddress((void**)&chunkS, g_chunkS);

    __nv_bfloat16* ab = nullptr;
    cudaGetSymbolAddress((void**)&ab, g_act);
    __nv_bfloat16* h_hi  = ab;
    __nv_bfloat16* h_lo  = ab + SZ;
    __nv_bfloat16* g_hi  = ab + 2 * SZ;
    __nv_bfloat16* g_lo  = ab + 3 * SZ;
    __nv_bfloat16* ff_hi = ab + 4 * SZ;
    __nv_bfloat16* ff_lo = ab + 8 * SZ;

    __nv_bfloat16* wts = nullptr;
    cudaGetSymbolAddress((void**)&wts, g_wts);
    __nv_bfloat16* qkvg_h = wts;             // [L][2048][512]
    __nv_bfloat16* qkvg_l = wts + 4 * W5;
    __nv_bfloat16* wo_h   = wts + 8 * W5;
    __nv_bfloat16* wo_l   = wts + 9 * W5;
    __nv_bfloat16* w1_h   = wts + 10 * W5;
    __nv_bfloat16* w1_l   = wts + 10 * W5 + WF;
    __nv_bfloat16* w2_h   = wts + 10 * W5 + 2 * WF;
    __nv_bfloat16* w2_l   = wts + 10 * W5 + 3 * WF;

    float* biasP = nullptr;
    cudaGetSymbolAddress((void**)&biasP, g_bias);

    const int RET2_SMEM = RET2_FLOATS * (int)sizeof(float);
    cudaFuncSetAttribute(ret_phase2,
                         cudaFuncAttributeMaxDynamicSharedMemorySize, RET2_SMEM);
    cudaFuncSetAttribute(tc_gemm,
                         cudaFuncAttributeMaxDynamicSharedMemorySize, GEMM_SMEM);

    dim3 wb(32, 8);
    dim3 gemmQKVG(2048 / 128, MROWS / 192);  // (16, 34)
    dim3 gemmO(DD / 128, MROWS / 192);       // (4, 34)
    dim3 gemmF1(FFN / 128, MROWS / 192);     // (16, 34)
    dim3 gemmF2(DD / 128, MROWS / 192);      // (4, 34)
    const int NRET = BB * HH * NCHUNK;       // 768

    for (int l = 0; l < LL; l++) {
        const size_t oQW = (size_t)l * 2048 * DD;
        const size_t oW  = (size_t)l * DD * DD;
        const size_t oF  = (size_t)l * DD * FFN;
        const size_t ob  = (size_t)l * DD;
        const size_t obf = (size_t)l * FFN;

        if (l == 0) {
            wconv5_kernel<<<dim3(16, 16, 5 * LL), wb>>>(Wq, Wk, Wv, Wg, Wo,
                                                        qkvg_h, qkvg_l, wo_h, wo_l);
            embed_ln_kernel<<<MROWS, 256>>>(tokens, emb, ln1w, ln1b, x, h_hi, h_lo,
                                            bq, bk, bv, bg, biasP);
        } else {
            layernorm_split_kernel<<<MROWS, 256>>>(x, ln1w + ob, ln1b + ob, h_hi, h_lo);
        }

        tc_gemm<<<gemmQKVG, 256, GEMM_SMEM>>>(h_hi, h_lo, qkvg_h + oQW, qkvg_l + oQW,
                                              biasP + (size_t)l * 2048, q,
                                              nullptr, nullptr, DD, 2048, 4);

        ret_phase1<<<NRET, 256>>>(q + SZ, q + 2 * SZ, chunkS);
        ret_phase2<<<NRET, 256, RET2_SMEM>>>(q, q + SZ, q + 2 * SZ, chunkS, ret);

        gnorm_gate_kernel<<<MROWS, 256>>>(ret, gnw + ob, gnb + ob, q + 3 * SZ,
                                          g_hi, g_lo);

        tc_gemm<<<gemmO, 256, GEMM_SMEM>>>(g_hi, g_lo, wo_h + oW, wo_l + oW,
                                           bo + ob, x, nullptr, nullptr, DD, DD, 2);

        if (l == 0) {
            wconv_kernel<<<dim3(FFN / 32, DD / 32, LL), wb>>>(w1, w1_h, w1_l, DD, FFN);
            wconv_kernel<<<dim3(DD / 32, FFN / 32, LL), wb>>>(w2, w2_h, w2_l, FFN, DD);
        }

        layernorm_split_kernel<<<MROWS, 256>>>(x, ln2w + ob, ln2b + ob, h_hi, h_lo);

        tc_gemm<<<gemmF1, 256, GEMM_SMEM>>>(h_hi, h_lo, w1_h + oF, w1_l + oF,
                                            b1 + obf, nullptr, ff_hi, ff_lo,
                                            DD, FFN, 3);
        tc_gemm<<<gemmF2, 256, GEMM_SMEM>>>(ff_hi, ff_lo, w2_h + oF, w2_l + oF,
                                            b2 + ob, x, nullptr, nullptr,
                                            FFN, DD, 2);
    }
}